// round 7
// baseline (speedup 1.0000x reference)
#include <cuda_runtime.h>
#include <cuda_bf16.h>
#include <math.h>
#include <stdint.h>

// Problem sizes (fixed)
#define BB 64     // batch
#define SS 512    // seq len
#define DD 512    // input dim
#define HH 512    // hidden

// ---------------------------------------------------------------------------
// Device scratch (allocation-free rule: device globals only)
// ---------------------------------------------------------------------------
__device__ float g_gi[(size_t)SS * BB * 3 * HH];   // [s][b][3H]
__device__ float g_f [(size_t)SS * BB * 2 * HH];   // [s][b][2H]
__device__ float g_h [2][BB * HH];                 // h ping-pong
__device__ unsigned g_bar[4];                      // per-batch-group barrier

__global__ void init_bar_kernel() {
    if (threadIdx.x < 4) g_bar[threadIdx.x] = 0u;
}

// ---------------------------------------------------------------------------
// mma.sync helpers (sm_80+ vocabulary — works under compute_103 PTX)
// ---------------------------------------------------------------------------
__device__ __forceinline__ uint32_t smem_to_u32(const void* p) {
    uint32_t a;
    asm("{ .reg .u64 t; cvta.to.shared.u64 t, %1; cvt.u32.u64 %0, t; }"
        : "=r"(a) : "l"(p));
    return a;
}

#define LDMATRIX_X4(r, addr) \
    asm volatile("ldmatrix.sync.aligned.m8n8.x4.shared.b16 {%0,%1,%2,%3}, [%4];" \
        : "=r"((r)[0]), "=r"((r)[1]), "=r"((r)[2]), "=r"((r)[3]) : "r"(addr))

#define MMA_BF16(d, a, b0, b1) \
    asm volatile("mma.sync.aligned.m16n8k16.row.col.f32.bf16.bf16.f32 " \
        "{%0,%1,%2,%3}, {%4,%5,%6,%7}, {%8,%9}, {%0,%1,%2,%3};" \
        : "+f"((d)[0]), "+f"((d)[1]), "+f"((d)[2]), "+f"((d)[3]) \
        : "r"((a)[0]), "r"((a)[1]), "r"((a)[2]), "r"((a)[3]), \
          "r"(b0), "r"(b1))

__device__ __forceinline__ uint32_t pack_bf16(float a, float b) {
    return ((uint32_t)__bfloat16_as_ushort(__float2bfloat16_rn(b)) << 16) |
           (uint32_t)__bfloat16_as_ushort(__float2bfloat16_rn(a));
}

// ---------------------------------------------------------------------------
// Precompute GEMMs (unchanged from passing round-5 kernel).
// CTA 128x128, BK=32, 512 threads (16 warps, 4x4), bf16 hi/lo 3-pass split.
// ---------------------------------------------------------------------------
#define GP 40                              // smem pitch in bf16 elements
#define G_TILE_B (128 * GP * 2)            // 10240 bytes per tile
#define OFF_AH(buf) ((buf) * 4 * G_TILE_B + 0 * G_TILE_B)
#define OFF_AL(buf) ((buf) * 4 * G_TILE_B + 1 * G_TILE_B)
#define OFF_BH(buf) ((buf) * 4 * G_TILE_B + 2 * G_TILE_B)
#define OFF_BL(buf) ((buf) * 4 * G_TILE_B + 3 * G_TILE_B)
#define GEMM_SMEM_BYTES (8 * G_TILE_B)     // 81920

__device__ __forceinline__ void ldg_chunk(const float* __restrict__ src,
                                          float4 v[2], int t) {
#pragma unroll
    for (int i = 0; i < 2; i++) {
        int idx = t + 512 * i;
        int row = idx >> 3;
        int kq  = idx & 7;
        v[i] = *(const float4*)(src + (size_t)row * 512 + kq * 4);
    }
}

__device__ __forceinline__ void sts_chunk(char* smem, int hi_off, int lo_off,
                                          const float4 v[2], int t) {
#pragma unroll
    for (int i = 0; i < 2; i++) {
        int idx = t + 512 * i;
        int row = idx >> 3;
        int kq  = idx & 7;
        float4 x = v[i];
        float hx = __bfloat162float(__float2bfloat16_rn(x.x));
        float hy = __bfloat162float(__float2bfloat16_rn(x.y));
        float hz = __bfloat162float(__float2bfloat16_rn(x.z));
        float hw = __bfloat162float(__float2bfloat16_rn(x.w));
        uint2 hi = make_uint2(pack_bf16(x.x, x.y), pack_bf16(x.z, x.w));
        uint2 lo = make_uint2(pack_bf16(x.x - hx, x.y - hy),
                              pack_bf16(x.z - hz, x.w - hw));
        uint32_t boff = (uint32_t)(row * GP + kq * 4) * 2;
        *(uint2*)(smem + hi_off + boff) = hi;
        *(uint2*)(smem + lo_off + boff) = lo;
    }
}

__device__ __forceinline__ void warp_k16(uint32_t sb, int buf, int ks,
                                         int wm, int wn, int lane,
                                         float acc[2][4][4]) {
    const int lr = lane & 7;
    const int lg = lane >> 3;
    uint32_t ah[2][4], al[2][4];
#pragma unroll
    for (int mt = 0; mt < 2; mt++) {
        int arow = wm * 32 + mt * 16 + lr + (lg & 1) * 8;
        int acol = ks * 16 + (lg >> 1) * 8;
        uint32_t boff = (uint32_t)(arow * GP + acol) * 2;
        LDMATRIX_X4(ah[mt], sb + OFF_AH(buf) + boff);
        LDMATRIX_X4(al[mt], sb + OFF_AL(buf) + boff);
    }
    uint32_t bh[2][4], bl[2][4];
#pragma unroll
    for (int np = 0; np < 2; np++) {
        int brow = wn * 32 + np * 16 + lr + (lg >> 1) * 8;
        int bcol = ks * 16 + (lg & 1) * 8;
        uint32_t boff = (uint32_t)(brow * GP + bcol) * 2;
        LDMATRIX_X4(bh[np], sb + OFF_BH(buf) + boff);
        LDMATRIX_X4(bl[np], sb + OFF_BL(buf) + boff);
    }
#pragma unroll
    for (int mt = 0; mt < 2; mt++)
#pragma unroll
        for (int np = 0; np < 2; np++)
#pragma unroll
            for (int sub = 0; sub < 2; sub++) {
                int nj = np * 2 + sub;
                MMA_BF16(acc[mt][nj], ah[mt], bh[np][2 * sub], bh[np][2 * sub + 1]);
                MMA_BF16(acc[mt][nj], ah[mt], bl[np][2 * sub], bl[np][2 * sub + 1]);
                MMA_BF16(acc[mt][nj], al[mt], bh[np][2 * sub], bh[np][2 * sub + 1]);
            }
}

__global__ __launch_bounds__(512, 1) void gemm_gi_mma(
    const float* __restrict__ A, const float* __restrict__ W,
    const float* __restrict__ bias)
{
    extern __shared__ char smem[];
    uint32_t sb = smem_to_u32(smem);
    const int t = threadIdx.x;
    const int wid = t >> 5;
    const int lane = t & 31;
    const int wm = wid & 3;
    const int wn = wid >> 2;
    const int m0 = blockIdx.x * 128;
    const int n0 = blockIdx.y * 128;

    float acc[2][4][4];
#pragma unroll
    for (int i = 0; i < 2; i++)
#pragma unroll
        for (int j = 0; j < 4; j++)
#pragma unroll
            for (int k = 0; k < 4; k++) acc[i][j][k] = 0.f;

    const float* Abase = A + (size_t)m0 * 512;
    const float* Wbase = W + (size_t)n0 * 512;

    float4 av[2], bv[2];
    ldg_chunk(Abase, av, t);
    ldg_chunk(Wbase, bv, t);
    sts_chunk(smem, OFF_AH(0), OFF_AL(0), av, t);
    sts_chunk(smem, OFF_BH(0), OFF_BL(0), bv, t);
    __syncthreads();

    const int NC = 16;
    for (int c = 0; c < NC; c++) {
        int buf = c & 1;
        if (c + 1 < NC) {
            ldg_chunk(Abase + (c + 1) * 32, av, t);
            ldg_chunk(Wbase + (c + 1) * 32, bv, t);
        }
        warp_k16(sb, buf, 0, wm, wn, lane, acc);
        warp_k16(sb, buf, 1, wm, wn, lane, acc);
        if (c + 1 < NC) {
            __syncthreads();
            sts_chunk(smem, OFF_AH(buf ^ 1), OFF_AL(buf ^ 1), av, t);
            sts_chunk(smem, OFF_BH(buf ^ 1), OFF_BL(buf ^ 1), bv, t);
            __syncthreads();
        }
    }

    const int qrow = lane >> 2;
    const int qcol = (lane & 3) * 2;
#pragma unroll
    for (int mt = 0; mt < 2; mt++)
#pragma unroll
        for (int half = 0; half < 2; half++) {
            int m = m0 + wm * 32 + mt * 16 + qrow + half * 8;
            int b = m >> 9;
            int s = m & 511;
            float* crow = &g_gi[((size_t)s * 64 + b) * 1536 + n0 + wn * 32];
#pragma unroll
            for (int nj = 0; nj < 4; nj++) {
                int n = nj * 8 + qcol;
                float2 bvv = *(const float2*)&bias[n0 + wn * 32 + n];
                float2 o;
                o.x = acc[mt][nj][half * 2 + 0] + bvv.x;
                o.y = acc[mt][nj][half * 2 + 1] + bvv.y;
                *(float2*)&crow[n] = o;
            }
        }
}

__global__ __launch_bounds__(512, 1) void gemm_f_mma(
    const float* __restrict__ Aux, const float* __restrict__ Wf,
    const float* __restrict__ bf)
{
    extern __shared__ char smem[];
    uint32_t sb = smem_to_u32(smem);
    const int t = threadIdx.x;
    const int wid = t >> 5;
    const int lane = t & 31;
    const int wm = wid & 3;
    const int wn = wid >> 2;
    const int m0 = blockIdx.x * 128;
    const int n0 = blockIdx.y * 128;

    float acc[2][4][4];
#pragma unroll
    for (int i = 0; i < 2; i++)
#pragma unroll
        for (int j = 0; j < 4; j++)
#pragma unroll
            for (int k = 0; k < 4; k++) acc[i][j][k] = 0.f;

    float4 av[2], bv[2];
    ldg_chunk(Aux + (size_t)m0 * 512, av, t);
    ldg_chunk(Wf + (size_t)n0 * 512, bv, t);
    sts_chunk(smem, OFF_AH(0), OFF_AL(0), av, t);
    sts_chunk(smem, OFF_BH(0), OFF_BL(0), bv, t);
    __syncthreads();

    const int NC = 32;
    for (int c = 0; c < NC; c++) {
        int buf = c & 1;
        if (c + 1 < NC) {
            int cn = c + 1;
            int seg = cn >> 4, kk = cn & 15;
            const float* An = Aux + (size_t)seg * 32768 * 512 + (size_t)m0 * 512 + kk * 32;
            const float* Wn = Wf + (size_t)seg * 1024 * 512 + (size_t)n0 * 512 + kk * 32;
            ldg_chunk(An, av, t);
            ldg_chunk(Wn, bv, t);
        }
        warp_k16(sb, buf, 0, wm, wn, lane, acc);
        warp_k16(sb, buf, 1, wm, wn, lane, acc);
        if (c + 1 < NC) {
            __syncthreads();
            sts_chunk(smem, OFF_AH(buf ^ 1), OFF_AL(buf ^ 1), av, t);
            sts_chunk(smem, OFF_BH(buf ^ 1), OFF_BL(buf ^ 1), bv, t);
            __syncthreads();
        }
    }

    const int qrow = lane >> 2;
    const int qcol = (lane & 3) * 2;
#pragma unroll
    for (int mt = 0; mt < 2; mt++)
#pragma unroll
        for (int half = 0; half < 2; half++) {
            int m = m0 + wm * 32 + mt * 16 + qrow + half * 8;
            int b = m >> 9;
            int s = m & 511;
            float* crow = &g_f[((size_t)s * 64 + b) * 1024 + n0 + wn * 32];
#pragma unroll
            for (int nj = 0; nj < 4; nj++) {
                int n = nj * 8 + qcol;
                int ng = n0 + wn * 32 + n;
                float2 b0 = *(const float2*)&bf[ng];
                float2 b1 = *(const float2*)&bf[1024 + ng];
                float2 o;
                o.x = 0.5f * acc[mt][nj][half * 2 + 0] + 0.5f * (b0.x + b1.x);
                o.y = 0.5f * acc[mt][nj][half * 2 + 1] + 0.5f * (b0.y + b1.y);
                *(float2*)&crow[n] = o;
            }
        }
}

// ---------------------------------------------------------------------------
// Persistent recurrent scan — MMA version, 512 threads (16 warps).
// Grid 128 = 4 batch-groups (16 b) x 32 column-CTAs (16 hy cols = 48 W rows).
// W_hh slice -> bf16 hi/lo fragments in REGISTERS (loaded once).
// Per step: h (16x512 fp32) -> bf16 hi/lo smem; 16 warps split K (32 each);
// 36 mma.sync per warp (3-pass hi/lo split); 16-way smem reduction; gates;
// red.release/ld.acquire global barrier over the 32-CTA group.
// ---------------------------------------------------------------------------
#define SPITCH 520                       // bf16 pitch (1040 B: 16B/row rotation)
#define S_OFF_WH  0                      // 48 x 520 bf16 = 49920 B
#define S_OFF_WL  49920                  // 49920 B
#define S_OFF_HH  99840                  // 16 x 520 bf16 = 16640 B
#define S_OFF_HL  116480                 // 16640 B
#define S_OFF_RED 133120                 // 16 x 768 fp32 = 49152 B
#define S_OFF_GHS 182272                 // 768 fp32 = 3072 B
#define S_OFF_BS  185344                 // 48 fp32 = 192 B
#define SCAN_SMEM_BYTES 185536

__global__ __launch_bounds__(512, 1) void scan_kernel(
    const float* __restrict__ hx, const float* __restrict__ Whh,
    const float* __restrict__ bias_hh, float* __restrict__ out)
{
    extern __shared__ char smem[];
    uint32_t sb = smem_to_u32(smem);
    float* redf = (float*)(smem + S_OFF_RED);
    float* ghs  = (float*)(smem + S_OFF_GHS);
    float* bs   = (float*)(smem + S_OFF_BS);

    const int t    = threadIdx.x;
    const int w    = t >> 5;               // warp 0..15 (K-slice 32 each)
    const int lane = t & 31;
    const int lr   = lane & 7;
    const int lg   = lane >> 3;
    const int gid  = blockIdx.x >> 5;      // batch group 0..3
    const int cid  = blockIdx.x & 31;      // column CTA 0..31
    const int b0   = gid * 16;
    const int c0   = cid * 16;

    // --- Stage W_hh slice (48 rows x 512) as bf16 hi/lo into smem ---
    for (int i = t; i < 48 * 128; i += 512) {
        int r = i >> 7;                    // 0..47
        int q = i & 127;                   // float4 index
        int gate = r >> 4, j = r & 15;
        float4 v = *(const float4*)&Whh[(size_t)(gate * 512 + c0 + j) * 512 + q * 4];
        float hx0 = __bfloat162float(__float2bfloat16_rn(v.x));
        float hy0 = __bfloat162float(__float2bfloat16_rn(v.y));
        float hz0 = __bfloat162float(__float2bfloat16_rn(v.z));
        float hw0 = __bfloat162float(__float2bfloat16_rn(v.w));
        uint2 hi = make_uint2(pack_bf16(v.x, v.y), pack_bf16(v.z, v.w));
        uint2 lo = make_uint2(pack_bf16(v.x - hx0, v.y - hy0),
                              pack_bf16(v.z - hz0, v.w - hw0));
        uint32_t boff = (uint32_t)(r * SPITCH + q * 4) * 2;
        *(uint2*)(smem + S_OFF_WH + boff) = hi;
        *(uint2*)(smem + S_OFF_WL + boff) = lo;
    }
    if (t < 48) {
        int gate = t >> 4, j = t & 15;
        bs[t] = bias_hh[gate * 512 + c0 + j];
    }
    __syncthreads();

    // --- Preload W fragments into registers (per warp: 3 n16-groups x 2 k16) ---
    uint32_t bfh[3][2][4], bfl[3][2][4];
#pragma unroll
    for (int np = 0; np < 3; np++)
#pragma unroll
        for (int ks = 0; ks < 2; ks++) {
            int brow = np * 16 + lr + (lg >> 1) * 8;
            int bcol = w * 32 + ks * 16 + (lg & 1) * 8;
            uint32_t boff = (uint32_t)(brow * SPITCH + bcol) * 2;
            LDMATRIX_X4(bfh[np][ks], sb + S_OFF_WH + boff);
            LDMATRIX_X4(bfl[np][ks], sb + S_OFF_WL + boff);
        }

    const int eb = (t & 255) >> 4;         // epilogue batch 0..15
    const int ej = t & 15;                 // epilogue column 0..15
    const int bglob = b0 + eb;
    const int qrow = lane >> 2;
    const int qcol = (lane & 3) * 2;

    unsigned* barp = &g_bar[gid];

    for (int s = 0; s < 512; s++) {
        const float* hsrc = (s == 0) ? (hx + (size_t)b0 * 512)
                                     : (g_h[s & 1] + (size_t)b0 * 512);
        // --- Convert h (16x512 fp32) to bf16 hi/lo smem ---
#pragma unroll
        for (int i = 0; i < 4; i++) {
            int idx = t + 512 * i;         // 0..2047
            int row = idx >> 7;            // 0..15
            int q   = idx & 127;
            float4 v = *(const float4*)&hsrc[(size_t)row * 512 + q * 4];
            float hx0 = __bfloat162float(__float2bfloat16_rn(v.x));
            float hy0 = __bfloat162float(__float2bfloat16_rn(v.y));
            float hz0 = __bfloat162float(__float2bfloat16_rn(v.z));
            float hw0 = __bfloat162float(__float2bfloat16_rn(v.w));
            uint2 hi = make_uint2(pack_bf16(v.x, v.y), pack_bf16(v.z, v.w));
            uint2 lo = make_uint2(pack_bf16(v.x - hx0, v.y - hy0),
                                  pack_bf16(v.z - hz0, v.w - hw0));
            uint32_t boff = (uint32_t)(row * SPITCH + q * 4) * 2;
            *(uint2*)(smem + S_OFF_HH + boff) = hi;
            *(uint2*)(smem + S_OFF_HL + boff) = lo;
        }

        // --- Prefetch gi / f / hprev (independent of MMA; epilogue threads) ---
        float i_r = 0.f, i_i = 0.f, i_n = 0.f, f_r = 0.f, f_i = 0.f, hprev = 0.f;
        if (t < 256) {
            size_t gib = ((size_t)s * 64 + bglob) * 1536 + c0 + ej;
            i_r = g_gi[gib];
            i_i = g_gi[gib + 512];
            i_n = g_gi[gib + 1024];
            size_t fb = ((size_t)s * 64 + bglob) * 1024 + c0 + ej;
            f_r = g_f[fb];
            f_i = g_f[fb + 512];
            hprev = hsrc[(size_t)eb * 512 + c0 + ej];
        }

        __syncthreads();   // h bf16 tiles visible

        // --- MMA phase: gh partial over warp's K-slice (32) ---
        float acc[6][4];
#pragma unroll
        for (int nj = 0; nj < 6; nj++)
#pragma unroll
            for (int k = 0; k < 4; k++) acc[nj][k] = 0.f;

#pragma unroll
        for (int ks = 0; ks < 2; ks++) {
            uint32_t ah[4], al[4];
            int arow = lr + (lg & 1) * 8;
            int acol = w * 32 + ks * 16 + (lg >> 1) * 8;
            uint32_t aoff = (uint32_t)(arow * SPITCH + acol) * 2;
            LDMATRIX_X4(ah, sb + S_OFF_HH + aoff);
            LDMATRIX_X4(al, sb + S_OFF_HL + aoff);
#pragma unroll
            for (int np = 0; np < 3; np++)
#pragma unroll
                for (int sub = 0; sub < 2; sub++) {
                    int nj = np * 2 + sub;
                    MMA_BF16(acc[nj], ah, bfh[np][ks][2 * sub], bfh[np][ks][2 * sub + 1]);
                    MMA_BF16(acc[nj], ah, bfl[np][ks][2 * sub], bfl[np][ks][2 * sub + 1]);
                    MMA_BF16(acc[nj], al, bfh[np][ks][2 * sub], bfh[np][ks][2 * sub + 1]);
                }
        }

        // --- Store partials [n48 x m16] per warp ---
        {
            float* red = redf + w * 768;
#pragma unroll
            for (int nj = 0; nj < 6; nj++)
#pragma unroll
                for (int half = 0; half < 2; half++) {
                    int m = qrow + half * 8;
                    int n = nj * 8 + qcol;
                    red[n * 16 + m]       = acc[nj][half * 2 + 0];
                    red[(n + 1) * 16 + m] = acc[nj][half * 2 + 1];
                }
        }
        __syncthreads();

        // --- 16-way reduction -> ghs[n*16+m] ---
        for (int o = t; o < 768; o += 512) {
            float acc_r = redf[o];
#pragma unroll
            for (int w2 = 1; w2 < 16; w2++) acc_r += redf[w2 * 768 + o];
            ghs[o] = acc_r;
        }
        __syncthreads();

        // --- Gate epilogue for (eb, ej): threads 0..255 ---
        if (t < 256) {
            float h_r = ghs[ej * 16 + eb]        + bs[ej];
            float h_i = ghs[(16 + ej) * 16 + eb] + bs[16 + ej];
            float h_n = ghs[(32 + ej) * 16 + eb] + bs[32 + ej];
            float rgate = 1.f / (1.f + expf(-(i_r + h_r + f_r)));
            float igate = 1.f / (1.f + expf(-(i_i + h_i + f_i)));
            float ngate = tanhf(i_n + rgate * h_n);
            float hy = ngate + igate * (hprev - ngate);

            g_h[(s + 1) & 1][(size_t)bglob * 512 + c0 + ej] = hy;
            out[((size_t)bglob * 512 + s) * 512 + c0 + ej] = hy;
            if (s == 511)
                out[(size_t)64 * 512 * 512 + (size_t)bglob * 512 + c0 + ej] = hy;
        }

        // --- Group barrier: release-arrive + acquire-spin ---
        __syncthreads();                   // all threads' hy stores done
        if (t == 0) {
            asm volatile("red.release.gpu.global.add.u32 [%0], %1;"
                         :: "l"(barp), "r"(1u) : "memory");
            unsigned target = (unsigned)(s + 1) * 32u;
            unsigned v;
            do {
                asm volatile("ld.acquire.gpu.global.u32 %0, [%1];"
                             : "=r"(v) : "l"(barp) : "memory");
            } while (v < target);
        }
        __syncthreads();
    }
}

// ---------------------------------------------------------------------------
// Launch
// ---------------------------------------------------------------------------
extern "C" void kernel_launch(void* const* d_in, const int* in_sizes, int n_in,
                              void* d_out, int out_size) {
    const float* input = (const float*)d_in[0];   // [B,S,D]
    const float* aux   = (const float*)d_in[1];   // [2,B,S,D]
    const float* hx    = (const float*)d_in[2];   // [B,H]
    const float* w_ih  = (const float*)d_in[3];   // [3H,D]
    const float* w_fh  = (const float*)d_in[4];   // [2,2H,D]
    const float* b_ih  = (const float*)d_in[5];   // [3H]
    const float* b_fh  = (const float*)d_in[6];   // [2,2H]
    const float* w_hh  = (const float*)d_in[7];   // [3H,H]
    const float* b_hh  = (const float*)d_in[8];   // [3H]
    float* out = (float*)d_out;

    cudaFuncSetAttribute(gemm_gi_mma,
                         cudaFuncAttributeMaxDynamicSharedMemorySize,
                         GEMM_SMEM_BYTES);
    cudaFuncSetAttribute(gemm_f_mma,
                         cudaFuncAttributeMaxDynamicSharedMemorySize,
                         GEMM_SMEM_BYTES);
    cudaFuncSetAttribute(scan_kernel,
                         cudaFuncAttributeMaxDynamicSharedMemorySize,
                         SCAN_SMEM_BYTES);

    init_bar_kernel<<<1, 32>>>();
    gemm_gi_mma<<<dim3(256, 12), 512, GEMM_SMEM_BYTES>>>(input, w_ih, b_ih);
    gemm_f_mma<<<dim3(256, 8), 512, GEMM_SMEM_BYTES>>>(aux, w_fh, b_fh);
    scan_kernel<<<128, 512, SCAN_SMEM_BYTES>>>(hx, w_hh, b_hh, out);
}

// round 8
// speedup vs baseline: 1.0611x; 1.0611x over previous
#include <cuda_runtime.h>
#include <cuda_bf16.h>
#include <math.h>
#include <stdint.h>

// Problem sizes (fixed)
#define BB 64     // batch
#define SS 512    // seq len
#define DD 512    // input dim
#define HH 512    // hidden

// ---------------------------------------------------------------------------
// Device scratch (allocation-free rule: device globals only)
// ---------------------------------------------------------------------------
__device__ float g_gi[(size_t)SS * BB * 3 * HH];   // [s][b][3H]
__device__ float g_f [(size_t)SS * BB * 2 * HH];   // [s][b][2H]
__device__ float g_h [2][BB * HH];                 // h ping-pong
__device__ unsigned g_bar[4];                      // per-batch-group barrier

__global__ void init_bar_kernel() {
    if (threadIdx.x < 4) g_bar[threadIdx.x] = 0u;
}

// ---------------------------------------------------------------------------
// mma.sync helpers (sm_80+ vocabulary — works under compute_103 PTX)
// ---------------------------------------------------------------------------
__device__ __forceinline__ uint32_t smem_to_u32(const void* p) {
    uint32_t a;
    asm("{ .reg .u64 t; cvta.to.shared.u64 t, %1; cvt.u32.u64 %0, t; }"
        : "=r"(a) : "l"(p));
    return a;
}

#define LDMATRIX_X4(r, addr) \
    asm volatile("ldmatrix.sync.aligned.m8n8.x4.shared.b16 {%0,%1,%2,%3}, [%4];" \
        : "=r"((r)[0]), "=r"((r)[1]), "=r"((r)[2]), "=r"((r)[3]) : "r"(addr))

#define MMA_BF16(d, a, b0, b1) \
    asm volatile("mma.sync.aligned.m16n8k16.row.col.f32.bf16.bf16.f32 " \
        "{%0,%1,%2,%3}, {%4,%5,%6,%7}, {%8,%9}, {%0,%1,%2,%3};" \
        : "+f"((d)[0]), "+f"((d)[1]), "+f"((d)[2]), "+f"((d)[3]) \
        : "r"((a)[0]), "r"((a)[1]), "r"((a)[2]), "r"((a)[3]), \
          "r"(b0), "r"(b1))

__device__ __forceinline__ uint32_t pack_bf16(float a, float b) {
    return ((uint32_t)__bfloat16_as_ushort(__float2bfloat16_rn(b)) << 16) |
           (uint32_t)__bfloat16_as_ushort(__float2bfloat16_rn(a));
}

// ---------------------------------------------------------------------------
// Precompute GEMMs: CTA 128x128, BK=32, 256 threads (8 warps, 2x4 grid,
// warp tile 64x32). bf16 hi/lo 3-pass split. Double-buffered smem.
// ---------------------------------------------------------------------------
#define GP 40                              // smem pitch in bf16 elements
#define G_TILE_B (128 * GP * 2)            // 10240 bytes per tile
#define OFF_AH(buf) ((buf) * 4 * G_TILE_B + 0 * G_TILE_B)
#define OFF_AL(buf) ((buf) * 4 * G_TILE_B + 1 * G_TILE_B)
#define OFF_BH(buf) ((buf) * 4 * G_TILE_B + 2 * G_TILE_B)
#define OFF_BL(buf) ((buf) * 4 * G_TILE_B + 3 * G_TILE_B)
#define GEMM_SMEM_BYTES (8 * G_TILE_B)     // 81920

// 256-thread loaders: [128 x 32] fp32 chunk = 1024 float4
__device__ __forceinline__ void ldg_chunk(const float* __restrict__ src,
                                          float4 v[4], int t) {
#pragma unroll
    for (int i = 0; i < 4; i++) {
        int idx = t + 256 * i;
        int row = idx >> 3;
        int kq  = idx & 7;
        v[i] = *(const float4*)(src + (size_t)row * 512 + kq * 4);
    }
}

__device__ __forceinline__ void sts_chunk(char* smem, int hi_off, int lo_off,
                                          const float4 v[4], int t) {
#pragma unroll
    for (int i = 0; i < 4; i++) {
        int idx = t + 256 * i;
        int row = idx >> 3;
        int kq  = idx & 7;
        float4 x = v[i];
        float hx = __bfloat162float(__float2bfloat16_rn(x.x));
        float hy = __bfloat162float(__float2bfloat16_rn(x.y));
        float hz = __bfloat162float(__float2bfloat16_rn(x.z));
        float hw = __bfloat162float(__float2bfloat16_rn(x.w));
        uint2 hi = make_uint2(pack_bf16(x.x, x.y), pack_bf16(x.z, x.w));
        uint2 lo = make_uint2(pack_bf16(x.x - hx, x.y - hy),
                              pack_bf16(x.z - hz, x.w - hw));
        uint32_t boff = (uint32_t)(row * GP + kq * 4) * 2;
        *(uint2*)(smem + hi_off + boff) = hi;
        *(uint2*)(smem + lo_off + boff) = lo;
    }
}

// One k16 step: warp tile 64(M) x 32(N): 12 ldmatrix.x4 + 48 mma.
__device__ __forceinline__ void warp_k16(uint32_t sb, int buf, int ks,
                                         int wm, int wn, int lane,
                                         float acc[4][4][4]) {
    const int lr = lane & 7;
    const int lg = lane >> 3;
    uint32_t ah[4][4], al[4][4];
#pragma unroll
    for (int mt = 0; mt < 4; mt++) {
        int arow = wm * 64 + mt * 16 + lr + (lg & 1) * 8;
        int acol = ks * 16 + (lg >> 1) * 8;
        uint32_t boff = (uint32_t)(arow * GP + acol) * 2;
        LDMATRIX_X4(ah[mt], sb + OFF_AH(buf) + boff);
        LDMATRIX_X4(al[mt], sb + OFF_AL(buf) + boff);
    }
    uint32_t bh[2][4], bl[2][4];
#pragma unroll
    for (int np = 0; np < 2; np++) {
        int brow = wn * 32 + np * 16 + lr + (lg >> 1) * 8;
        int bcol = ks * 16 + (lg & 1) * 8;
        uint32_t boff = (uint32_t)(brow * GP + bcol) * 2;
        LDMATRIX_X4(bh[np], sb + OFF_BH(buf) + boff);
        LDMATRIX_X4(bl[np], sb + OFF_BL(buf) + boff);
    }
#pragma unroll
    for (int mt = 0; mt < 4; mt++)
#pragma unroll
        for (int np = 0; np < 2; np++)
#pragma unroll
            for (int sub = 0; sub < 2; sub++) {
                int nj = np * 2 + sub;
                MMA_BF16(acc[mt][nj], ah[mt], bh[np][2 * sub], bh[np][2 * sub + 1]);
                MMA_BF16(acc[mt][nj], ah[mt], bl[np][2 * sub], bl[np][2 * sub + 1]);
                MMA_BF16(acc[mt][nj], al[mt], bh[np][2 * sub], bh[np][2 * sub + 1]);
            }
}

__global__ __launch_bounds__(256, 1) void gemm_gi_mma(
    const float* __restrict__ A, const float* __restrict__ W,
    const float* __restrict__ bias)
{
    extern __shared__ char smem[];
    uint32_t sb = smem_to_u32(smem);
    const int t = threadIdx.x;
    const int wid = t >> 5;
    const int lane = t & 31;
    const int wm = wid & 1;
    const int wn = wid >> 1;
    const int m0 = blockIdx.x * 128;
    const int n0 = blockIdx.y * 128;

    float acc[4][4][4];
#pragma unroll
    for (int i = 0; i < 4; i++)
#pragma unroll
        for (int j = 0; j < 4; j++)
#pragma unroll
            for (int k = 0; k < 4; k++) acc[i][j][k] = 0.f;

    const float* Abase = A + (size_t)m0 * 512;
    const float* Wbase = W + (size_t)n0 * 512;

    float4 av[4], bv[4];
    ldg_chunk(Abase, av, t);
    ldg_chunk(Wbase, bv, t);
    sts_chunk(smem, OFF_AH(0), OFF_AL(0), av, t);
    sts_chunk(smem, OFF_BH(0), OFF_BL(0), bv, t);
    __syncthreads();

    const int NC = 16;
    for (int c = 0; c < NC; c++) {
        int buf = c & 1;
        if (c + 1 < NC) {
            ldg_chunk(Abase + (c + 1) * 32, av, t);
            ldg_chunk(Wbase + (c + 1) * 32, bv, t);
        }
        warp_k16(sb, buf, 0, wm, wn, lane, acc);
        warp_k16(sb, buf, 1, wm, wn, lane, acc);
        if (c + 1 < NC) {
            __syncthreads();
            sts_chunk(smem, OFF_AH(buf ^ 1), OFF_AL(buf ^ 1), av, t);
            sts_chunk(smem, OFF_BH(buf ^ 1), OFF_BL(buf ^ 1), bv, t);
            __syncthreads();
        }
    }

    const int qrow = lane >> 2;
    const int qcol = (lane & 3) * 2;
#pragma unroll
    for (int mt = 0; mt < 4; mt++)
#pragma unroll
        for (int half = 0; half < 2; half++) {
            int m = m0 + wm * 64 + mt * 16 + qrow + half * 8;
            int b = m >> 9;
            int s = m & 511;
            float* crow = &g_gi[((size_t)s * 64 + b) * 1536 + n0 + wn * 32];
#pragma unroll
            for (int nj = 0; nj < 4; nj++) {
                int n = nj * 8 + qcol;
                float2 bvv = *(const float2*)&bias[n0 + wn * 32 + n];
                float2 o;
                o.x = acc[mt][nj][half * 2 + 0] + bvv.x;
                o.y = acc[mt][nj][half * 2 + 1] + bvv.y;
                *(float2*)&crow[n] = o;
            }
        }
}

__global__ __launch_bounds__(256, 1) void gemm_f_mma(
    const float* __restrict__ Aux, const float* __restrict__ Wf,
    const float* __restrict__ bf)
{
    extern __shared__ char smem[];
    uint32_t sb = smem_to_u32(smem);
    const int t = threadIdx.x;
    const int wid = t >> 5;
    const int lane = t & 31;
    const int wm = wid & 1;
    const int wn = wid >> 1;
    const int m0 = blockIdx.x * 128;
    const int n0 = blockIdx.y * 128;

    float acc[4][4][4];
#pragma unroll
    for (int i = 0; i < 4; i++)
#pragma unroll
        for (int j = 0; j < 4; j++)
#pragma unroll
            for (int k = 0; k < 4; k++) acc[i][j][k] = 0.f;

    float4 av[4], bv[4];
    ldg_chunk(Aux + (size_t)m0 * 512, av, t);
    ldg_chunk(Wf + (size_t)n0 * 512, bv, t);
    sts_chunk(smem, OFF_AH(0), OFF_AL(0), av, t);
    sts_chunk(smem, OFF_BH(0), OFF_BL(0), bv, t);
    __syncthreads();

    const int NC = 32;
    for (int c = 0; c < NC; c++) {
        int buf = c & 1;
        if (c + 1 < NC) {
            int cn = c + 1;
            int seg = cn >> 4, kk = cn & 15;
            const float* An = Aux + (size_t)seg * 32768 * 512 + (size_t)m0 * 512 + kk * 32;
            const float* Wn = Wf + (size_t)seg * 1024 * 512 + (size_t)n0 * 512 + kk * 32;
            ldg_chunk(An, av, t);
            ldg_chunk(Wn, bv, t);
        }
        warp_k16(sb, buf, 0, wm, wn, lane, acc);
        warp_k16(sb, buf, 1, wm, wn, lane, acc);
        if (c + 1 < NC) {
            __syncthreads();
            sts_chunk(smem, OFF_AH(buf ^ 1), OFF_AL(buf ^ 1), av, t);
            sts_chunk(smem, OFF_BH(buf ^ 1), OFF_BL(buf ^ 1), bv, t);
            __syncthreads();
        }
    }

    const int qrow = lane >> 2;
    const int qcol = (lane & 3) * 2;
#pragma unroll
    for (int mt = 0; mt < 4; mt++)
#pragma unroll
        for (int half = 0; half < 2; half++) {
            int m = m0 + wm * 64 + mt * 16 + qrow + half * 8;
            int b = m >> 9;
            int s = m & 511;
            float* crow = &g_f[((size_t)s * 64 + b) * 1024 + n0 + wn * 32];
#pragma unroll
            for (int nj = 0; nj < 4; nj++) {
                int n = nj * 8 + qcol;
                int ng = n0 + wn * 32 + n;
                float2 b0 = *(const float2*)&bf[ng];
                float2 b1 = *(const float2*)&bf[1024 + ng];
                float2 o;
                o.x = 0.5f * acc[mt][nj][half * 2 + 0] + 0.5f * (b0.x + b1.x);
                o.y = 0.5f * acc[mt][nj][half * 2 + 1] + 0.5f * (b0.y + b1.y);
                *(float2*)&crow[n] = o;
            }
        }
}

// ---------------------------------------------------------------------------
// Persistent recurrent scan — MMA version, 256 threads (R5 config).
// Grid 128 = 4 batch-groups (16 b) x 32 column-CTAs (16 hy cols = 48 W rows).
// Barrier released BEFORE the out-row store (out consumed by nobody).
// ---------------------------------------------------------------------------
#define SPITCH 520                       // bf16 pitch
#define S_OFF_WH  0                      // 48 x 520 bf16 = 49920 B
#define S_OFF_WL  49920
#define S_OFF_HH  99840                  // 16 x 520 bf16 = 16640 B
#define S_OFF_HL  116480
#define S_OFF_RED 133120                 // 8 x 768 fp32 = 24576 B
#define S_OFF_GHS 157696                 // 768 fp32
#define S_OFF_BS  160768                 // 48 fp32
#define SCAN_SMEM_BYTES 160960

__global__ __launch_bounds__(256, 1) void scan_kernel(
    const float* __restrict__ hx, const float* __restrict__ Whh,
    const float* __restrict__ bias_hh, float* __restrict__ out)
{
    extern __shared__ char smem[];
    uint32_t sb = smem_to_u32(smem);
    float* redf = (float*)(smem + S_OFF_RED);
    float* ghs  = (float*)(smem + S_OFF_GHS);
    float* bs   = (float*)(smem + S_OFF_BS);

    const int t    = threadIdx.x;
    const int w    = t >> 5;               // warp 0..7 (K-slice 64 each)
    const int lane = t & 31;
    const int lr   = lane & 7;
    const int lg   = lane >> 3;
    const int gid  = blockIdx.x >> 5;
    const int cid  = blockIdx.x & 31;
    const int b0   = gid * 16;
    const int c0   = cid * 16;

    for (int i = t; i < 48 * 128; i += 256) {
        int r = i >> 7;
        int q = i & 127;
        int gate = r >> 4, j = r & 15;
        float4 v = *(const float4*)&Whh[(size_t)(gate * 512 + c0 + j) * 512 + q * 4];
        float hx0 = __bfloat162float(__float2bfloat16_rn(v.x));
        float hy0 = __bfloat162float(__float2bfloat16_rn(v.y));
        float hz0 = __bfloat162float(__float2bfloat16_rn(v.z));
        float hw0 = __bfloat162float(__float2bfloat16_rn(v.w));
        uint2 hi = make_uint2(pack_bf16(v.x, v.y), pack_bf16(v.z, v.w));
        uint2 lo = make_uint2(pack_bf16(v.x - hx0, v.y - hy0),
                              pack_bf16(v.z - hz0, v.w - hw0));
        uint32_t boff = (uint32_t)(r * SPITCH + q * 4) * 2;
        *(uint2*)(smem + S_OFF_WH + boff) = hi;
        *(uint2*)(smem + S_OFF_WL + boff) = lo;
    }
    if (t < 48) {
        int gate = t >> 4, j = t & 15;
        bs[t] = bias_hh[gate * 512 + c0 + j];
    }
    __syncthreads();

    // W fragments in registers: per warp 3 n16-groups x 4 k16 (hi/lo)
    uint32_t bfh[3][4][4], bfl[3][4][4];
#pragma unroll
    for (int np = 0; np < 3; np++)
#pragma unroll
        for (int ks = 0; ks < 4; ks++) {
            int brow = np * 16 + lr + (lg >> 1) * 8;
            int bcol = w * 64 + ks * 16 + (lg & 1) * 8;
            uint32_t boff = (uint32_t)(brow * SPITCH + bcol) * 2;
            LDMATRIX_X4(bfh[np][ks], sb + S_OFF_WH + boff);
            LDMATRIX_X4(bfl[np][ks], sb + S_OFF_WL + boff);
        }

    const int eb = t >> 4;
    const int ej = t & 15;
    const int bglob = b0 + eb;
    const int qrow = lane >> 2;
    const int qcol = (lane & 3) * 2;

    unsigned* barp = &g_bar[gid];

    for (int s = 0; s < 512; s++) {
        const float* hsrc = (s == 0) ? (hx + (size_t)b0 * 512)
                                     : (g_h[s & 1] + (size_t)b0 * 512);
#pragma unroll
        for (int i = 0; i < 8; i++) {
            int idx = t + 256 * i;
            int row = idx >> 7;
            int q   = idx & 127;
            float4 v = *(const float4*)&hsrc[(size_t)row * 512 + q * 4];
            float hx0 = __bfloat162float(__float2bfloat16_rn(v.x));
            float hy0 = __bfloat162float(__float2bfloat16_rn(v.y));
            float hz0 = __bfloat162float(__float2bfloat16_rn(v.z));
            float hw0 = __bfloat162float(__float2bfloat16_rn(v.w));
            uint2 hi = make_uint2(pack_bf16(v.x, v.y), pack_bf16(v.z, v.w));
            uint2 lo = make_uint2(pack_bf16(v.x - hx0, v.y - hy0),
                                  pack_bf16(v.z - hz0, v.w - hw0));
            uint32_t boff = (uint32_t)(row * SPITCH + q * 4) * 2;
            *(uint2*)(smem + S_OFF_HH + boff) = hi;
            *(uint2*)(smem + S_OFF_HL + boff) = lo;
        }

        size_t gib = ((size_t)s * 64 + bglob) * 1536 + c0 + ej;
        float i_r = g_gi[gib];
        float i_i = g_gi[gib + 512];
        float i_n = g_gi[gib + 1024];
        size_t fb = ((size_t)s * 64 + bglob) * 1024 + c0 + ej;
        float f_r = g_f[fb];
        float f_i = g_f[fb + 512];
        float hprev = hsrc[(size_t)eb * 512 + c0 + ej];

        __syncthreads();

        float acc[6][4];
#pragma unroll
        for (int nj = 0; nj < 6; nj++)
#pragma unroll
            for (int k = 0; k < 4; k++) acc[nj][k] = 0.f;

#pragma unroll
        for (int ks = 0; ks < 4; ks++) {
            uint32_t ah[4], al[4];
            int arow = lr + (lg & 1) * 8;
            int acol = w * 64 + ks * 16 + (lg >> 1) * 8;
            uint32_t aoff = (uint32_t)(arow * SPITCH + acol) * 2;
            LDMATRIX_X4(ah, sb + S_OFF_HH + aoff);
            LDMATRIX_X4(al, sb + S_OFF_HL + aoff);
#pragma unroll
            for (int np = 0; np < 3; np++)
#pragma unroll
                for (int sub = 0; sub < 2; sub++) {
                    int nj = np * 2 + sub;
                    MMA_BF16(acc[nj], ah, bfh[np][ks][2 * sub], bfh[np][ks][2 * sub + 1]);
                    MMA_BF16(acc[nj], ah, bfl[np][ks][2 * sub], bfl[np][ks][2 * sub + 1]);
                    MMA_BF16(acc[nj], al, bfh[np][ks][2 * sub], bfh[np][ks][2 * sub + 1]);
                }
        }

        {
            float* red = redf + w * 768;
#pragma unroll
            for (int nj = 0; nj < 6; nj++)
#pragma unroll
                for (int half = 0; half < 2; half++) {
                    int m = qrow + half * 8;
                    int n = nj * 8 + qcol;
                    red[n * 16 + m]       = acc[nj][half * 2 + 0];
                    red[(n + 1) * 16 + m] = acc[nj][half * 2 + 1];
                }
        }
        __syncthreads();

#pragma unroll
        for (int j = 0; j < 3; j++) {
            int o = t + 256 * j;
            float acc_r = redf[o];
#pragma unroll
            for (int w2 = 1; w2 < 8; w2++) acc_r += redf[w2 * 768 + o];
            ghs[o] = acc_r;
        }
        __syncthreads();

        float h_r = ghs[ej * 16 + eb]        + bs[ej];
        float h_i = ghs[(16 + ej) * 16 + eb] + bs[16 + ej];
        float h_n = ghs[(32 + ej) * 16 + eb] + bs[32 + ej];
        float rgate = 1.f / (1.f + __expf(-(i_r + h_r + f_r)));
        float igate = 1.f / (1.f + __expf(-(i_i + h_i + f_i)));
        float ngate = tanhf(i_n + rgate * h_n);
        float hy = ngate + igate * (hprev - ngate);

        // h for next step first — this is the only store others wait for
        g_h[(s + 1) & 1][(size_t)bglob * 512 + c0 + ej] = hy;

        __syncthreads();                   // all hy stores issued
        if (t == 0) {
            asm volatile("red.release.gpu.global.add.u32 [%0], %1;"
                         :: "l"(barp), "r"(1u) : "memory");
        }

        // out-row store overlaps other CTAs' barrier arrival
        out[((size_t)bglob * 512 + s) * 512 + c0 + ej] = hy;
        if (s == 511)
            out[(size_t)64 * 512 * 512 + (size_t)bglob * 512 + c0 + ej] = hy;

        if (t == 0) {
            unsigned target = (unsigned)(s + 1) * 32u;
            unsigned v;
            do {
                asm volatile("ld.acquire.gpu.global.u32 %0, [%1];"
                             : "=r"(v) : "l"(barp) : "memory");
            } while (v < target);
        }
        __syncthreads();
    }
}

// ---------------------------------------------------------------------------
// Launch
// ---------------------------------------------------------------------------
extern "C" void kernel_launch(void* const* d_in, const int* in_sizes, int n_in,
                              void* d_out, int out_size) {
    const float* input = (const float*)d_in[0];   // [B,S,D]
    const float* aux   = (const float*)d_in[1];   // [2,B,S,D]
    const float* hx    = (const float*)d_in[2];   // [B,H]
    const float* w_ih  = (const float*)d_in[3];   // [3H,D]
    const float* w_fh  = (const float*)d_in[4];   // [2,2H,D]
    const float* b_ih  = (const float*)d_in[5];   // [3H]
    const float* b_fh  = (const float*)d_in[6];   // [2,2H]
    const float* w_hh  = (const float*)d_in[7];   // [3H,H]
    const float* b_hh  = (const float*)d_in[8];   // [3H]
    float* out = (float*)d_out;

    cudaFuncSetAttribute(gemm_gi_mma,
                         cudaFuncAttributeMaxDynamicSharedMemorySize,
                         GEMM_SMEM_BYTES);
    cudaFuncSetAttribute(gemm_f_mma,
                         cudaFuncAttributeMaxDynamicSharedMemorySize,
                         GEMM_SMEM_BYTES);
    cudaFuncSetAttribute(scan_kernel,
                         cudaFuncAttributeMaxDynamicSharedMemorySize,
                         SCAN_SMEM_BYTES);

    init_bar_kernel<<<1, 32>>>();
    gemm_gi_mma<<<dim3(256, 12), 256, GEMM_SMEM_BYTES>>>(input, w_ih, b_ih);
    gemm_f_mma<<<dim3(256, 8), 256, GEMM_SMEM_BYTES>>>(aux, w_fh, b_fh);
    scan_kernel<<<128, 256, SCAN_SMEM_BYTES>>>(hx, w_hh, b_hh, out);
}

// round 10
// speedup vs baseline: 1.1225x; 1.0579x over previous
#include <cuda_runtime.h>
#include <cuda_bf16.h>
#include <math.h>
#include <stdint.h>

// Problem sizes (fixed)
#define BB 64     // batch
#define SS 512    // seq len
#define DD 512    // input dim
#define HH 512    // hidden

// ---------------------------------------------------------------------------
// Device scratch (allocation-free rule: device globals only)
// ---------------------------------------------------------------------------
__device__ float g_gi[(size_t)SS * BB * 3 * HH];   // [s][b][3H]
__device__ float g_f [(size_t)SS * BB * 2 * HH];   // [s][b][2H]
__device__ __nv_bfloat16 g_hh[2][BB * HH];         // h hi-plane ping-pong
__device__ __nv_bfloat16 g_hl[2][BB * HH];         // h lo-plane ping-pong
__device__ unsigned g_bar[4];                      // per-batch-group barrier

__global__ void init_bar_kernel() {
    if (threadIdx.x < 4) g_bar[threadIdx.x] = 0u;
}

// ---------------------------------------------------------------------------
// mma.sync helpers (sm_80+ vocabulary — works under compute_103 PTX)
// ---------------------------------------------------------------------------
__device__ __forceinline__ uint32_t smem_to_u32(const void* p) {
    uint32_t a;
    asm("{ .reg .u64 t; cvta.to.shared.u64 t, %1; cvt.u32.u64 %0, t; }"
        : "=r"(a) : "l"(p));
    return a;
}

#define LDMATRIX_X4(r, addr) \
    asm volatile("ldmatrix.sync.aligned.m8n8.x4.shared.b16 {%0,%1,%2,%3}, [%4];" \
        : "=r"((r)[0]), "=r"((r)[1]), "=r"((r)[2]), "=r"((r)[3]) : "r"(addr))

#define MMA_BF16(d, a, b0, b1) \
    asm volatile("mma.sync.aligned.m16n8k16.row.col.f32.bf16.bf16.f32 " \
        "{%0,%1,%2,%3}, {%4,%5,%6,%7}, {%8,%9}, {%0,%1,%2,%3};" \
        : "+f"((d)[0]), "+f"((d)[1]), "+f"((d)[2]), "+f"((d)[3]) \
        : "r"((a)[0]), "r"((a)[1]), "r"((a)[2]), "r"((a)[3]), \
          "r"(b0), "r"(b1))

__device__ __forceinline__ uint32_t pack_bf16(float a, float b) {
    return ((uint32_t)__bfloat16_as_ushort(__float2bfloat16_rn(b)) << 16) |
           (uint32_t)__bfloat16_as_ushort(__float2bfloat16_rn(a));
}

// ---------------------------------------------------------------------------
// Precompute GEMMs (unchanged from passing round-8 kernel).
// CTA 128x128, BK=32, 256 threads (8 warps, 2x4, warp tile 64x32).
// ---------------------------------------------------------------------------
#define GP 40                              // smem pitch in bf16 elements
#define G_TILE_B (128 * GP * 2)            // 10240 bytes per tile
#define OFF_AH(buf) ((buf) * 4 * G_TILE_B + 0 * G_TILE_B)
#define OFF_AL(buf) ((buf) * 4 * G_TILE_B + 1 * G_TILE_B)
#define OFF_BH(buf) ((buf) * 4 * G_TILE_B + 2 * G_TILE_B)
#define OFF_BL(buf) ((buf) * 4 * G_TILE_B + 3 * G_TILE_B)
#define GEMM_SMEM_BYTES (8 * G_TILE_B)     // 81920

__device__ __forceinline__ void ldg_chunk(const float* __restrict__ src,
                                          float4 v[4], int t) {
#pragma unroll
    for (int i = 0; i < 4; i++) {
        int idx = t + 256 * i;
        int row = idx >> 3;
        int kq  = idx & 7;
        v[i] = *(const float4*)(src + (size_t)row * 512 + kq * 4);
    }
}

__device__ __forceinline__ void sts_chunk(char* smem, int hi_off, int lo_off,
                                          const float4 v[4], int t) {
#pragma unroll
    for (int i = 0; i < 4; i++) {
        int idx = t + 256 * i;
        int row = idx >> 3;
        int kq  = idx & 7;
        float4 x = v[i];
        float hx = __bfloat162float(__float2bfloat16_rn(x.x));
        float hy = __bfloat162float(__float2bfloat16_rn(x.y));
        float hz = __bfloat162float(__float2bfloat16_rn(x.z));
        float hw = __bfloat162float(__float2bfloat16_rn(x.w));
        uint2 hi = make_uint2(pack_bf16(x.x, x.y), pack_bf16(x.z, x.w));
        uint2 lo = make_uint2(pack_bf16(x.x - hx, x.y - hy),
                              pack_bf16(x.z - hz, x.w - hw));
        uint32_t boff = (uint32_t)(row * GP + kq * 4) * 2;
        *(uint2*)(smem + hi_off + boff) = hi;
        *(uint2*)(smem + lo_off + boff) = lo;
    }
}

__device__ __forceinline__ void warp_k16(uint32_t sb, int buf, int ks,
                                         int wm, int wn, int lane,
                                         float acc[4][4][4]) {
    const int lr = lane & 7;
    const int lg = lane >> 3;
    uint32_t ah[4][4], al[4][4];
#pragma unroll
    for (int mt = 0; mt < 4; mt++) {
        int arow = wm * 64 + mt * 16 + lr + (lg & 1) * 8;
        int acol = ks * 16 + (lg >> 1) * 8;
        uint32_t boff = (uint32_t)(arow * GP + acol) * 2;
        LDMATRIX_X4(ah[mt], sb + OFF_AH(buf) + boff);
        LDMATRIX_X4(al[mt], sb + OFF_AL(buf) + boff);
    }
    uint32_t bh[2][4], bl[2][4];
#pragma unroll
    for (int np = 0; np < 2; np++) {
        int brow = wn * 32 + np * 16 + lr + (lg >> 1) * 8;
        int bcol = ks * 16 + (lg & 1) * 8;
        uint32_t boff = (uint32_t)(brow * GP + bcol) * 2;
        LDMATRIX_X4(bh[np], sb + OFF_BH(buf) + boff);
        LDMATRIX_X4(bl[np], sb + OFF_BL(buf) + boff);
    }
#pragma unroll
    for (int mt = 0; mt < 4; mt++)
#pragma unroll
        for (int np = 0; np < 2; np++)
#pragma unroll
            for (int sub = 0; sub < 2; sub++) {
                int nj = np * 2 + sub;
                MMA_BF16(acc[mt][nj], ah[mt], bh[np][2 * sub], bh[np][2 * sub + 1]);
                MMA_BF16(acc[mt][nj], ah[mt], bl[np][2 * sub], bl[np][2 * sub + 1]);
                MMA_BF16(acc[mt][nj], al[mt], bh[np][2 * sub], bh[np][2 * sub + 1]);
            }
}

__global__ __launch_bounds__(256, 1) void gemm_gi_mma(
    const float* __restrict__ A, const float* __restrict__ W,
    const float* __restrict__ bias)
{
    extern __shared__ char smem[];
    uint32_t sb = smem_to_u32(smem);
    const int t = threadIdx.x;
    const int wid = t >> 5;
    const int lane = t & 31;
    const int wm = wid & 1;
    const int wn = wid >> 1;
    const int m0 = blockIdx.x * 128;
    const int n0 = blockIdx.y * 128;

    float acc[4][4][4];
#pragma unroll
    for (int i = 0; i < 4; i++)
#pragma unroll
        for (int j = 0; j < 4; j++)
#pragma unroll
            for (int k = 0; k < 4; k++) acc[i][j][k] = 0.f;

    const float* Abase = A + (size_t)m0 * 512;
    const float* Wbase = W + (size_t)n0 * 512;

    float4 av[4], bv[4];
    ldg_chunk(Abase, av, t);
    ldg_chunk(Wbase, bv, t);
    sts_chunk(smem, OFF_AH(0), OFF_AL(0), av, t);
    sts_chunk(smem, OFF_BH(0), OFF_BL(0), bv, t);
    __syncthreads();

    const int NC = 16;
    for (int c = 0; c < NC; c++) {
        int buf = c & 1;
        if (c + 1 < NC) {
            ldg_chunk(Abase + (c + 1) * 32, av, t);
            ldg_chunk(Wbase + (c + 1) * 32, bv, t);
        }
        warp_k16(sb, buf, 0, wm, wn, lane, acc);
        warp_k16(sb, buf, 1, wm, wn, lane, acc);
        if (c + 1 < NC) {
            __syncthreads();
            sts_chunk(smem, OFF_AH(buf ^ 1), OFF_AL(buf ^ 1), av, t);
            sts_chunk(smem, OFF_BH(buf ^ 1), OFF_BL(buf ^ 1), bv, t);
            __syncthreads();
        }
    }

    const int qrow = lane >> 2;
    const int qcol = (lane & 3) * 2;
#pragma unroll
    for (int mt = 0; mt < 4; mt++)
#pragma unroll
        for (int half = 0; half < 2; half++) {
            int m = m0 + wm * 64 + mt * 16 + qrow + half * 8;
            int b = m >> 9;
            int s = m & 511;
            float* crow = &g_gi[((size_t)s * 64 + b) * 1536 + n0 + wn * 32];
#pragma unroll
            for (int nj = 0; nj < 4; nj++) {
                int n = nj * 8 + qcol;
                float2 bvv = *(const float2*)&bias[n0 + wn * 32 + n];
                float2 o;
                o.x = acc[mt][nj][half * 2 + 0] + bvv.x;
                o.y = acc[mt][nj][half * 2 + 1] + bvv.y;
                *(float2*)&crow[n] = o;
            }
        }
}

__global__ __launch_bounds__(256, 1) void gemm_f_mma(
    const float* __restrict__ Aux, const float* __restrict__ Wf,
    const float* __restrict__ bf)
{
    extern __shared__ char smem[];
    uint32_t sb = smem_to_u32(smem);
    const int t = threadIdx.x;
    const int wid = t >> 5;
    const int lane = t & 31;
    const int wm = wid & 1;
    const int wn = wid >> 1;
    const int m0 = blockIdx.x * 128;
    const int n0 = blockIdx.y * 128;

    float acc[4][4][4];
#pragma unroll
    for (int i = 0; i < 4; i++)
#pragma unroll
        for (int j = 0; j < 4; j++)
#pragma unroll
            for (int k = 0; k < 4; k++) acc[i][j][k] = 0.f;

    float4 av[4], bv[4];
    ldg_chunk(Aux + (size_t)m0 * 512, av, t);
    ldg_chunk(Wf + (size_t)n0 * 512, bv, t);
    sts_chunk(smem, OFF_AH(0), OFF_AL(0), av, t);
    sts_chunk(smem, OFF_BH(0), OFF_BL(0), bv, t);
    __syncthreads();

    const int NC = 32;
    for (int c = 0; c < NC; c++) {
        int buf = c & 1;
        if (c + 1 < NC) {
            int cn = c + 1;
            int seg = cn >> 4, kk = cn & 15;
            const float* An = Aux + (size_t)seg * 32768 * 512 + (size_t)m0 * 512 + kk * 32;
            const float* Wn = Wf + (size_t)seg * 1024 * 512 + (size_t)n0 * 512 + kk * 32;
            ldg_chunk(An, av, t);
            ldg_chunk(Wn, bv, t);
        }
        warp_k16(sb, buf, 0, wm, wn, lane, acc);
        warp_k16(sb, buf, 1, wm, wn, lane, acc);
        if (c + 1 < NC) {
            __syncthreads();
            sts_chunk(smem, OFF_AH(buf ^ 1), OFF_AL(buf ^ 1), av, t);
            sts_chunk(smem, OFF_BH(buf ^ 1), OFF_BL(buf ^ 1), bv, t);
            __syncthreads();
        }
    }

    const int qrow = lane >> 2;
    const int qcol = (lane & 3) * 2;
#pragma unroll
    for (int mt = 0; mt < 4; mt++)
#pragma unroll
        for (int half = 0; half < 2; half++) {
            int m = m0 + wm * 64 + mt * 16 + qrow + half * 8;
            int b = m >> 9;
            int s = m & 511;
            float* crow = &g_f[((size_t)s * 64 + b) * 1024 + n0 + wn * 32];
#pragma unroll
            for (int nj = 0; nj < 4; nj++) {
                int n = nj * 8 + qcol;
                int ng = n0 + wn * 32 + n;
                float2 b0 = *(const float2*)&bf[ng];
                float2 b1 = *(const float2*)&bf[1024 + ng];
                float2 o;
                o.x = 0.5f * acc[mt][nj][half * 2 + 0] + 0.5f * (b0.x + b1.x);
                o.y = 0.5f * acc[mt][nj][half * 2 + 1] + 0.5f * (b0.y + b1.y);
                *(float2*)&crow[n] = o;
            }
        }
}

// ---------------------------------------------------------------------------
// Persistent recurrent scan — 256 threads, producer-side bf16 hi/lo h
// exchange (staging = pure copy), reduction fused into gate epilogue.
// Grid 128 = 4 batch-groups (16 b) x 32 column-CTAs (16 hy cols = 48 W rows).
// ---------------------------------------------------------------------------
#define SPITCH 520                       // bf16 pitch
#define S_OFF_WH  0                      // 48 x 520 bf16 = 49920 B
#define S_OFF_WL  49920
#define S_OFF_HH  99840                  // 16 x 520 bf16 = 16640 B
#define S_OFF_HL  116480
#define S_OFF_RED 133120                 // 8 x 784 fp32 = 25088 B
#define S_OFF_BS  158208                 // 48 fp32
#define SCAN_SMEM_BYTES 158400

__global__ __launch_bounds__(256, 1) void scan_kernel(
    const float* __restrict__ hx, const float* __restrict__ Whh,
    const float* __restrict__ bias_hh, float* __restrict__ out)
{
    extern __shared__ char smem[];
    uint32_t sb = smem_to_u32(smem);
    float* redf = (float*)(smem + S_OFF_RED);
    float* bs   = (float*)(smem + S_OFF_BS);

    const int t    = threadIdx.x;
    const int w    = t >> 5;               // warp 0..7 (K-slice 64 each)
    const int lane = t & 31;
    const int lr   = lane & 7;
    const int lg   = lane >> 3;
    const int gid  = blockIdx.x >> 5;
    const int cid  = blockIdx.x & 31;
    const int b0   = gid * 16;
    const int c0   = cid * 16;

    // --- Stage W_hh slice as bf16 hi/lo into smem (once) ---
    for (int i = t; i < 48 * 128; i += 256) {
        int r = i >> 7;
        int q = i & 127;
        int gate = r >> 4, j = r & 15;
        float4 v = *(const float4*)&Whh[(size_t)(gate * 512 + c0 + j) * 512 + q * 4];
        float hx0 = __bfloat162float(__float2bfloat16_rn(v.x));
        float hy0 = __bfloat162float(__float2bfloat16_rn(v.y));
        float hz0 = __bfloat162float(__float2bfloat16_rn(v.z));
        float hw0 = __bfloat162float(__float2bfloat16_rn(v.w));
        uint2 hi = make_uint2(pack_bf16(v.x, v.y), pack_bf16(v.z, v.w));
        uint2 lo = make_uint2(pack_bf16(v.x - hx0, v.y - hy0),
                              pack_bf16(v.z - hz0, v.w - hw0));
        uint32_t boff = (uint32_t)(r * SPITCH + q * 4) * 2;
        *(uint2*)(smem + S_OFF_WH + boff) = hi;
        *(uint2*)(smem + S_OFF_WL + boff) = lo;
    }
    if (t < 48) {
        int gate = t >> 4, j = t & 15;
        bs[t] = bias_hh[gate * 512 + c0 + j];
    }
    __syncthreads();

    // --- W fragments in registers: per warp 3 n16-groups x 4 k16 (hi/lo) ---
    uint32_t bfh[3][4][4], bfl[3][4][4];
#pragma unroll
    for (int np = 0; np < 3; np++)
#pragma unroll
        for (int ks = 0; ks < 4; ks++) {
            int brow = np * 16 + lr + (lg >> 1) * 8;
            int bcol = w * 64 + ks * 16 + (lg & 1) * 8;
            uint32_t boff = (uint32_t)(brow * SPITCH + bcol) * 2;
            LDMATRIX_X4(bfh[np][ks], sb + S_OFF_WH + boff);
            LDMATRIX_X4(bfl[np][ks], sb + S_OFF_WL + boff);
        }

    const int eb = t >> 4;                 // epilogue batch 0..15
    const int ej = t & 15;                 // epilogue column 0..15
    const int bglob = b0 + eb;
    const int qrow = lane >> 2;
    const int qcol = (lane & 3) * 2;

    unsigned* barp = &g_bar[gid];

    // hprev carried in register (exact fp32): this thread owns (bglob, c0+ej)
    float hprev = hx[(size_t)bglob * 512 + c0 + ej];

    for (int s = 0; s < 512; s++) {
        if (s == 0) {
            // One-time: convert hx (fp32) into hi/lo planes in smem
            const float* hsrc = hx + (size_t)b0 * 512;
#pragma unroll
            for (int i = 0; i < 8; i++) {
                int idx = t + 256 * i;
                int row = idx >> 7;
                int q   = idx & 127;
                float4 v = *(const float4*)&hsrc[(size_t)row * 512 + q * 4];
                float hx0 = __bfloat162float(__float2bfloat16_rn(v.x));
                float hy0 = __bfloat162float(__float2bfloat16_rn(v.y));
                float hz0 = __bfloat162float(__float2bfloat16_rn(v.z));
                float hw0 = __bfloat162float(__float2bfloat16_rn(v.w));
                uint2 hi = make_uint2(pack_bf16(v.x, v.y), pack_bf16(v.z, v.w));
                uint2 lo = make_uint2(pack_bf16(v.x - hx0, v.y - hy0),
                                      pack_bf16(v.z - hz0, v.w - hw0));
                uint32_t boff = (uint32_t)(row * SPITCH + q * 4) * 2;
                *(uint2*)(smem + S_OFF_HH + boff) = hi;
                *(uint2*)(smem + S_OFF_HL + boff) = lo;
            }
        } else {
            // Pure copy: 16 rows x 512 bf16 per plane = 64 uint4 per row
            const uint4* hh = (const uint4*)(g_hh[s & 1] + (size_t)b0 * 512);
            const uint4* hl = (const uint4*)(g_hl[s & 1] + (size_t)b0 * 512);
#pragma unroll
            for (int i = 0; i < 4; i++) {
                int idx = t + 256 * i;       // 0..1023
                int row = idx >> 6;          // 0..15
                int q   = idx & 63;
                uint32_t boff = (uint32_t)(row * SPITCH) * 2 + q * 16;
                *(uint4*)(smem + S_OFF_HH + boff) = hh[row * 64 + q];
                *(uint4*)(smem + S_OFF_HL + boff) = hl[row * 64 + q];
            }
        }

        // --- Prefetch gi / f (independent of MMA) ---
        size_t gib = ((size_t)s * 64 + bglob) * 1536 + c0 + ej;
        float i_r = g_gi[gib];
        float i_i = g_gi[gib + 512];
        float i_n = g_gi[gib + 1024];
        size_t fb = ((size_t)s * 64 + bglob) * 1024 + c0 + ej;
        float f_r = g_f[fb];
        float f_i = g_f[fb + 512];

        __syncthreads();   // h planes visible

        // --- MMA phase: gh partial over warp's K-slice (64) ---
        float acc[6][4];
#pragma unroll
        for (int nj = 0; nj < 6; nj++)
#pragma unroll
            for (int k = 0; k < 4; k++) acc[nj][k] = 0.f;

#pragma unroll
        for (int ks = 0; ks < 4; ks++) {
            uint32_t ah[4], al[4];
            int arow = lr + (lg & 1) * 8;
            int acol = w * 64 + ks * 16 + (lg >> 1) * 8;
            uint32_t aoff = (uint32_t)(arow * SPITCH + acol) * 2;
            LDMATRIX_X4(ah, sb + S_OFF_HH + aoff);
            LDMATRIX_X4(al, sb + S_OFF_HL + aoff);
#pragma unroll
            for (int np = 0; np < 3; np++)
#pragma unroll
                for (int sub = 0; sub < 2; sub++) {
                    int nj = np * 2 + sub;
                    MMA_BF16(acc[nj], ah, bfh[np][ks][2 * sub], bfh[np][ks][2 * sub + 1]);
                    MMA_BF16(acc[nj], ah, bfl[np][ks][2 * sub], bfl[np][ks][2 * sub + 1]);
                    MMA_BF16(acc[nj], al, bfh[np][ks][2 * sub], bfh[np][ks][2 * sub + 1]);
                }
        }

        // --- Store partials [m16 x n48], pitch 49 ---
        {
            float* red = redf + w * 784;
#pragma unroll
            for (int nj = 0; nj < 6; nj++)
#pragma unroll
                for (int half = 0; half < 2; half++) {
                    int m = qrow + half * 8;
                    int n = nj * 8 + qcol;
                    red[m * 49 + n]     = acc[nj][half * 2 + 0];
                    red[m * 49 + n + 1] = acc[nj][half * 2 + 1];
                }
        }
        __syncthreads();

        // --- Fused reduce + gate epilogue for (eb, ej) ---
        float h_r = bs[ej];
        float h_i = bs[16 + ej];
        float h_n = bs[32 + ej];
#pragma unroll
        for (int w2 = 0; w2 < 8; w2++) {
            const float* rr = redf + w2 * 784 + eb * 49;
            h_r += rr[ej];
            h_i += rr[16 + ej];
            h_n += rr[32 + ej];
        }
        float rgate = 1.f / (1.f + __expf(-(i_r + h_r + f_r)));
        float igate = 1.f / (1.f + __expf(-(i_i + h_i + f_i)));
        float ngate = tanhf(i_n + rgate * h_n);
        float hy = ngate + igate * (hprev - ngate);
        hprev = hy;

        // h for next step, hi/lo planes (conversion at the producer)
        {
            __nv_bfloat16 hhi = __float2bfloat16_rn(hy);
            float resid = hy - __bfloat162float(hhi);
            __nv_bfloat16 hlo = __float2bfloat16_rn(resid);
            size_t hidx = (size_t)bglob * 512 + c0 + ej;
            g_hh[(s + 1) & 1][hidx] = hhi;
            g_hl[(s + 1) & 1][hidx] = hlo;
        }

        __syncthreads();                   // all hy stores issued
        if (t == 0) {
            asm volatile("red.release.gpu.global.add.u32 [%0], %1;"
                         :: "l"(barp), "r"(1u) : "memory");
        }

        // out-row store overlaps other CTAs' barrier arrival
        out[((size_t)bglob * 512 + s) * 512 + c0 + ej] = hy;
        if (s == 511)
            out[(size_t)64 * 512 * 512 + (size_t)bglob * 512 + c0 + ej] = hy;

        if (t == 0) {
            unsigned target = (unsigned)(s + 1) * 32u;
            unsigned v;
            do {
                asm volatile("ld.acquire.gpu.global.u32 %0, [%1];"
                             : "=r"(v) : "l"(barp) : "memory");
            } while (v < target);
        }
        __syncthreads();
    }
}

// ---------------------------------------------------------------------------
// Launch
// ---------------------------------------------------------------------------
extern "C" void kernel_launch(void* const* d_in, const int* in_sizes, int n_in,
                              void* d_out, int out_size) {
    const float* input = (const float*)d_in[0];   // [B,S,D]
    const float* aux   = (const float*)d_in[1];   // [2,B,S,D]
    const float* hx    = (const float*)d_in[2];   // [B,H]
    const float* w_ih  = (const float*)d_in[3];   // [3H,D]
    const float* w_fh  = (const float*)d_in[4];   // [2,2H,D]
    const float* b_ih  = (const float*)d_in[5];   // [3H]
    const float* b_fh  = (const float*)d_in[6];   // [2,2H]
    const float* w_hh  = (const float*)d_in[7];   // [3H,H]
    const float* b_hh  = (const float*)d_in[8];   // [3H]
    float* out = (float*)d_out;

    cudaFuncSetAttribute(gemm_gi_mma,
                         cudaFuncAttributeMaxDynamicSharedMemorySize,
                         GEMM_SMEM_BYTES);
    cudaFuncSetAttribute(gemm_f_mma,
                         cudaFuncAttributeMaxDynamicSharedMemorySize,
                         GEMM_SMEM_BYTES);
    cudaFuncSetAttribute(scan_kernel,
                         cudaFuncAttributeMaxDynamicSharedMemorySize,
                         SCAN_SMEM_BYTES);

    init_bar_kernel<<<1, 32>>>();
    gemm_gi_mma<<<dim3(256, 12), 256, GEMM_SMEM_BYTES>>>(input, w_ih, b_ih);
    gemm_f_mma<<<dim3(256, 8), 256, GEMM_SMEM_BYTES>>>(aux, w_fh, b_fh);
    scan_kernel<<<128, 256, SCAN_SMEM_BYTES>>>(hx, w_hh, b_hh, out);
}

// round 11
// speedup vs baseline: 1.1492x; 1.0238x over previous
#include <cuda_runtime.h>
#include <cuda_bf16.h>
#include <math.h>
#include <stdint.h>

// Problem sizes (fixed)
#define BB 64     // batch
#define SS 512    // seq len
#define DD 512    // input dim
#define HH 512    // hidden

// ---------------------------------------------------------------------------
// Device scratch (allocation-free rule: device globals only)
// ---------------------------------------------------------------------------
__device__ float g_gi[(size_t)SS * BB * 3 * HH];   // [s][b][3H]
__device__ float g_f [(size_t)SS * BB * 2 * HH];   // [s][b][2H]
__device__ __nv_bfloat16 g_hh[2][BB * HH];         // h hi-plane ping-pong
__device__ __nv_bfloat16 g_hl[2][BB * HH];         // h lo-plane ping-pong
__device__ unsigned g_bar[4];                      // per-batch-group barrier

__global__ void init_bar_kernel() {
    if (threadIdx.x < 4) g_bar[threadIdx.x] = 0u;
}

// ---------------------------------------------------------------------------
// mma.sync helpers (sm_80+ vocabulary — works under compute_103 PTX)
// ---------------------------------------------------------------------------
__device__ __forceinline__ uint32_t smem_to_u32(const void* p) {
    uint32_t a;
    asm("{ .reg .u64 t; cvta.to.shared.u64 t, %1; cvt.u32.u64 %0, t; }"
        : "=r"(a) : "l"(p));
    return a;
}

#define LDMATRIX_X4(r, addr) \
    asm volatile("ldmatrix.sync.aligned.m8n8.x4.shared.b16 {%0,%1,%2,%3}, [%4];" \
        : "=r"((r)[0]), "=r"((r)[1]), "=r"((r)[2]), "=r"((r)[3]) : "r"(addr))

#define MMA_BF16(d, a, b0, b1) \
    asm volatile("mma.sync.aligned.m16n8k16.row.col.f32.bf16.bf16.f32 " \
        "{%0,%1,%2,%3}, {%4,%5,%6,%7}, {%8,%9}, {%0,%1,%2,%3};" \
        : "+f"((d)[0]), "+f"((d)[1]), "+f"((d)[2]), "+f"((d)[3]) \
        : "r"((a)[0]), "r"((a)[1]), "r"((a)[2]), "r"((a)[3]), \
          "r"(b0), "r"(b1))

__device__ __forceinline__ uint32_t pack_bf16(float a, float b) {
    return ((uint32_t)__bfloat16_as_ushort(__float2bfloat16_rn(b)) << 16) |
           (uint32_t)__bfloat16_as_ushort(__float2bfloat16_rn(a));
}

// ---------------------------------------------------------------------------
// Precompute GEMMs: CTA 128x128, BK=64, 256 threads (8 warps, 2x4, warp tile
// 64x32). bf16 hi/lo 3-pass split. Double-buffered, ONE sync per 64-K chunk:
// prefetch LDG -> 2x warp_k16 (covers latency) -> STS into idle buffer ->
// 2x warp_k16 -> sync.
// ---------------------------------------------------------------------------
#define GP2 72                             // smem pitch in bf16 (144 B rows)
#define G2_TILE_B (128 * GP2 * 2)          // 18432 bytes per tile
#define OFF2(st, w) ((st) * 4 * G2_TILE_B + (w) * G2_TILE_B)
#define GEMM_SMEM_BYTES (8 * G2_TILE_B)    // 147456

// Load one [128 x 32] fp32 sub-chunk (row stride 512): 4 float4 per thread.
__device__ __forceinline__ void ldg_sub(const float* __restrict__ src,
                                        float4 v[4], int t) {
#pragma unroll
    for (int i = 0; i < 4; i++) {
        int idx = t + 256 * i;
        int row = idx >> 3;
        int kq  = idx & 7;
        v[i] = *(const float4*)(src + (size_t)row * 512 + kq * 4);
    }
}

// Convert + store one sub-chunk into hi/lo tiles at K offset ksub*32.
__device__ __forceinline__ void sts_sub(char* smem, int hi_off, int lo_off,
                                        const float4 v[4], int t, int ksub) {
#pragma unroll
    for (int i = 0; i < 4; i++) {
        int idx = t + 256 * i;
        int row = idx >> 3;
        int kq  = idx & 7;
        float4 x = v[i];
        float hx = __bfloat162float(__float2bfloat16_rn(x.x));
        float hy = __bfloat162float(__float2bfloat16_rn(x.y));
        float hz = __bfloat162float(__float2bfloat16_rn(x.z));
        float hw = __bfloat162float(__float2bfloat16_rn(x.w));
        uint2 hi = make_uint2(pack_bf16(x.x, x.y), pack_bf16(x.z, x.w));
        uint2 lo = make_uint2(pack_bf16(x.x - hx, x.y - hy),
                              pack_bf16(x.z - hz, x.w - hw));
        uint32_t boff = (uint32_t)(row * GP2 + ksub * 32 + kq * 4) * 2;
        *(uint2*)(smem + hi_off + boff) = hi;
        *(uint2*)(smem + lo_off + boff) = lo;
    }
}

// One k16 step: warp tile 64(M) x 32(N): 12 ldmatrix.x4 + 48 mma.
__device__ __forceinline__ void warp_k16(uint32_t sb, int buf, int ks,
                                         int wm, int wn, int lane,
                                         float acc[4][4][4]) {
    const int lr = lane & 7;
    const int lg = lane >> 3;
    uint32_t ah[4][4], al[4][4];
#pragma unroll
    for (int mt = 0; mt < 4; mt++) {
        int arow = wm * 64 + mt * 16 + lr + (lg & 1) * 8;
        int acol = ks * 16 + (lg >> 1) * 8;
        uint32_t boff = (uint32_t)(arow * GP2 + acol) * 2;
        LDMATRIX_X4(ah[mt], sb + OFF2(buf, 0) + boff);
        LDMATRIX_X4(al[mt], sb + OFF2(buf, 1) + boff);
    }
    uint32_t bh[2][4], bl[2][4];
#pragma unroll
    for (int np = 0; np < 2; np++) {
        int brow = wn * 32 + np * 16 + lr + (lg >> 1) * 8;
        int bcol = ks * 16 + (lg & 1) * 8;
        uint32_t boff = (uint32_t)(brow * GP2 + bcol) * 2;
        LDMATRIX_X4(bh[np], sb + OFF2(buf, 2) + boff);
        LDMATRIX_X4(bl[np], sb + OFF2(buf, 3) + boff);
    }
#pragma unroll
    for (int mt = 0; mt < 4; mt++)
#pragma unroll
        for (int np = 0; np < 2; np++)
#pragma unroll
            for (int sub = 0; sub < 2; sub++) {
                int nj = np * 2 + sub;
                MMA_BF16(acc[mt][nj], ah[mt], bh[np][2 * sub], bh[np][2 * sub + 1]);
                MMA_BF16(acc[mt][nj], ah[mt], bl[np][2 * sub], bl[np][2 * sub + 1]);
                MMA_BF16(acc[mt][nj], al[mt], bh[np][2 * sub], bh[np][2 * sub + 1]);
            }
}

__global__ __launch_bounds__(256, 1) void gemm_gi_mma(
    const float* __restrict__ A, const float* __restrict__ W,
    const float* __restrict__ bias)
{
    extern __shared__ char smem[];
    uint32_t sb = smem_to_u32(smem);
    const int t = threadIdx.x;
    const int wid = t >> 5;
    const int lane = t & 31;
    const int wm = wid & 1;
    const int wn = wid >> 1;
    const int m0 = blockIdx.x * 128;
    const int n0 = blockIdx.y * 128;

    float acc[4][4][4];
#pragma unroll
    for (int i = 0; i < 4; i++)
#pragma unroll
        for (int j = 0; j < 4; j++)
#pragma unroll
            for (int k = 0; k < 4; k++) acc[i][j][k] = 0.f;

    const float* Abase = A + (size_t)m0 * 512;
    const float* Wbase = W + (size_t)n0 * 512;

    float4 a0[4], a1[4], b0[4], b1[4];
    // Fill buffer 0 with chunk 0 (K 0..63)
    ldg_sub(Abase, a0, t);
    ldg_sub(Abase + 32, a1, t);
    ldg_sub(Wbase, b0, t);
    ldg_sub(Wbase + 32, b1, t);
    sts_sub(smem, OFF2(0, 0), OFF2(0, 1), a0, t, 0);
    sts_sub(smem, OFF2(0, 0), OFF2(0, 1), a1, t, 1);
    sts_sub(smem, OFF2(0, 2), OFF2(0, 3), b0, t, 0);
    sts_sub(smem, OFF2(0, 2), OFF2(0, 3), b1, t, 1);
    __syncthreads();

    const int NC = 8;   // 512 / 64
    for (int c = 0; c < NC; c++) {
        int buf = c & 1;
        if (c + 1 < NC) {
            const float* Ac = Abase + (c + 1) * 64;
            const float* Wc = Wbase + (c + 1) * 64;
            ldg_sub(Ac, a0, t);
            ldg_sub(Ac + 32, a1, t);
            ldg_sub(Wc, b0, t);
            ldg_sub(Wc + 32, b1, t);
        }
        warp_k16(sb, buf, 0, wm, wn, lane, acc);
        warp_k16(sb, buf, 1, wm, wn, lane, acc);
        if (c + 1 < NC) {
            int nb = buf ^ 1;
            sts_sub(smem, OFF2(nb, 0), OFF2(nb, 1), a0, t, 0);
            sts_sub(smem, OFF2(nb, 0), OFF2(nb, 1), a1, t, 1);
            sts_sub(smem, OFF2(nb, 2), OFF2(nb, 3), b0, t, 0);
            sts_sub(smem, OFF2(nb, 2), OFF2(nb, 3), b1, t, 1);
        }
        warp_k16(sb, buf, 2, wm, wn, lane, acc);
        warp_k16(sb, buf, 3, wm, wn, lane, acc);
        __syncthreads();
    }

    const int qrow = lane >> 2;
    const int qcol = (lane & 3) * 2;
#pragma unroll
    for (int mt = 0; mt < 4; mt++)
#pragma unroll
        for (int half = 0; half < 2; half++) {
            int m = m0 + wm * 64 + mt * 16 + qrow + half * 8;
            int b = m >> 9;
            int s = m & 511;
            float* crow = &g_gi[((size_t)s * 64 + b) * 1536 + n0 + wn * 32];
#pragma unroll
            for (int nj = 0; nj < 4; nj++) {
                int n = nj * 8 + qcol;
                float2 bvv = *(const float2*)&bias[n0 + wn * 32 + n];
                float2 o;
                o.x = acc[mt][nj][half * 2 + 0] + bvv.x;
                o.y = acc[mt][nj][half * 2 + 1] + bvv.y;
                *(float2*)&crow[n] = o;
            }
        }
}

__global__ __launch_bounds__(256, 1) void gemm_f_mma(
    const float* __restrict__ Aux, const float* __restrict__ Wf,
    const float* __restrict__ bf)
{
    extern __shared__ char smem[];
    uint32_t sb = smem_to_u32(smem);
    const int t = threadIdx.x;
    const int wid = t >> 5;
    const int lane = t & 31;
    const int wm = wid & 1;
    const int wn = wid >> 1;
    const int m0 = blockIdx.x * 128;
    const int n0 = blockIdx.y * 128;

    float acc[4][4][4];
#pragma unroll
    for (int i = 0; i < 4; i++)
#pragma unroll
        for (int j = 0; j < 4; j++)
#pragma unroll
            for (int k = 0; k < 4; k++) acc[i][j][k] = 0.f;

    float4 a0[4], a1[4], b0[4], b1[4];
    const float* A0 = Aux + (size_t)m0 * 512;
    const float* W0 = Wf + (size_t)n0 * 512;
    ldg_sub(A0, a0, t);
    ldg_sub(A0 + 32, a1, t);
    ldg_sub(W0, b0, t);
    ldg_sub(W0 + 32, b1, t);
    sts_sub(smem, OFF2(0, 0), OFF2(0, 1), a0, t, 0);
    sts_sub(smem, OFF2(0, 0), OFF2(0, 1), a1, t, 1);
    sts_sub(smem, OFF2(0, 2), OFF2(0, 3), b0, t, 0);
    sts_sub(smem, OFF2(0, 2), OFF2(0, 3), b1, t, 1);
    __syncthreads();

    const int NC = 16;  // 2 segments x 8 chunks of 64K
    for (int c = 0; c < NC; c++) {
        int buf = c & 1;
        if (c + 1 < NC) {
            int cn = c + 1;
            int seg = cn >> 3, kk = cn & 7;
            const float* Ac = Aux + (size_t)seg * 32768 * 512 + (size_t)m0 * 512 + kk * 64;
            const float* Wc = Wf + (size_t)seg * 1024 * 512 + (size_t)n0 * 512 + kk * 64;
            ldg_sub(Ac, a0, t);
            ldg_sub(Ac + 32, a1, t);
            ldg_sub(Wc, b0, t);
            ldg_sub(Wc + 32, b1, t);
        }
        warp_k16(sb, buf, 0, wm, wn, lane, acc);
        warp_k16(sb, buf, 1, wm, wn, lane, acc);
        if (c + 1 < NC) {
            int nb = buf ^ 1;
            sts_sub(smem, OFF2(nb, 0), OFF2(nb, 1), a0, t, 0);
            sts_sub(smem, OFF2(nb, 0), OFF2(nb, 1), a1, t, 1);
            sts_sub(smem, OFF2(nb, 2), OFF2(nb, 3), b0, t, 0);
            sts_sub(smem, OFF2(nb, 2), OFF2(nb, 3), b1, t, 1);
        }
        warp_k16(sb, buf, 2, wm, wn, lane, acc);
        warp_k16(sb, buf, 3, wm, wn, lane, acc);
        __syncthreads();
    }

    const int qrow = lane >> 2;
    const int qcol = (lane & 3) * 2;
#pragma unroll
    for (int mt = 0; mt < 4; mt++)
#pragma unroll
        for (int half = 0; half < 2; half++) {
            int m = m0 + wm * 64 + mt * 16 + qrow + half * 8;
            int b = m >> 9;
            int s = m & 511;
            float* crow = &g_f[((size_t)s * 64 + b) * 1024 + n0 + wn * 32];
#pragma unroll
            for (int nj = 0; nj < 4; nj++) {
                int n = nj * 8 + qcol;
                int ng = n0 + wn * 32 + n;
                float2 c0 = *(const float2*)&bf[ng];
                float2 c1 = *(const float2*)&bf[1024 + ng];
                float2 o;
                o.x = 0.5f * acc[mt][nj][half * 2 + 0] + 0.5f * (c0.x + c1.x);
                o.y = 0.5f * acc[mt][nj][half * 2 + 1] + 0.5f * (c0.y + c1.y);
                *(float2*)&crow[n] = o;
            }
        }
}

// ---------------------------------------------------------------------------
// Persistent recurrent scan — byte-identical to the passing round-10 kernel.
// 256 threads, producer-side bf16 hi/lo h exchange, fused reduce+epilogue.
// Grid 128 = 4 batch-groups (16 b) x 32 column-CTAs (16 hy cols = 48 W rows).
// ---------------------------------------------------------------------------
#define SPITCH 520                       // bf16 pitch
#define S_OFF_WH  0                      // 48 x 520 bf16 = 49920 B
#define S_OFF_WL  49920
#define S_OFF_HH  99840                  // 16 x 520 bf16 = 16640 B
#define S_OFF_HL  116480
#define S_OFF_RED 133120                 // 8 x 784 fp32 = 25088 B
#define S_OFF_BS  158208                 // 48 fp32
#define SCAN_SMEM_BYTES 158400

__global__ __launch_bounds__(256, 1) void scan_kernel(
    const float* __restrict__ hx, const float* __restrict__ Whh,
    const float* __restrict__ bias_hh, float* __restrict__ out)
{
    extern __shared__ char smem[];
    uint32_t sb = smem_to_u32(smem);
    float* redf = (float*)(smem + S_OFF_RED);
    float* bs   = (float*)(smem + S_OFF_BS);

    const int t    = threadIdx.x;
    const int w    = t >> 5;               // warp 0..7 (K-slice 64 each)
    const int lane = t & 31;
    const int lr   = lane & 7;
    const int lg   = lane >> 3;
    const int gid  = blockIdx.x >> 5;
    const int cid  = blockIdx.x & 31;
    const int b0   = gid * 16;
    const int c0   = cid * 16;

    // --- Stage W_hh slice as bf16 hi/lo into smem (once) ---
    for (int i = t; i < 48 * 128; i += 256) {
        int r = i >> 7;
        int q = i & 127;
        int gate = r >> 4, j = r & 15;
        float4 v = *(const float4*)&Whh[(size_t)(gate * 512 + c0 + j) * 512 + q * 4];
        float hx0 = __bfloat162float(__float2bfloat16_rn(v.x));
        float hy0 = __bfloat162float(__float2bfloat16_rn(v.y));
        float hz0 = __bfloat162float(__float2bfloat16_rn(v.z));
        float hw0 = __bfloat162float(__float2bfloat16_rn(v.w));
        uint2 hi = make_uint2(pack_bf16(v.x, v.y), pack_bf16(v.z, v.w));
        uint2 lo = make_uint2(pack_bf16(v.x - hx0, v.y - hy0),
                              pack_bf16(v.z - hz0, v.w - hw0));
        uint32_t boff = (uint32_t)(r * SPITCH + q * 4) * 2;
        *(uint2*)(smem + S_OFF_WH + boff) = hi;
        *(uint2*)(smem + S_OFF_WL + boff) = lo;
    }
    if (t < 48) {
        int gate = t >> 4, j = t & 15;
        bs[t] = bias_hh[gate * 512 + c0 + j];
    }
    __syncthreads();

    // --- W fragments in registers: per warp 3 n16-groups x 4 k16 (hi/lo) ---
    uint32_t bfh[3][4][4], bfl[3][4][4];
#pragma unroll
    for (int np = 0; np < 3; np++)
#pragma unroll
        for (int ks = 0; ks < 4; ks++) {
            int brow = np * 16 + lr + (lg >> 1) * 8;
            int bcol = w * 64 + ks * 16 + (lg & 1) * 8;
            uint32_t boff = (uint32_t)(brow * SPITCH + bcol) * 2;
            LDMATRIX_X4(bfh[np][ks], sb + S_OFF_WH + boff);
            LDMATRIX_X4(bfl[np][ks], sb + S_OFF_WL + boff);
        }

    const int eb = t >> 4;                 // epilogue batch 0..15
    const int ej = t & 15;                 // epilogue column 0..15
    const int bglob = b0 + eb;
    const int qrow = lane >> 2;
    const int qcol = (lane & 3) * 2;

    unsigned* barp = &g_bar[gid];

    // hprev carried in register (exact fp32): this thread owns (bglob, c0+ej)
    float hprev = hx[(size_t)bglob * 512 + c0 + ej];

    for (int s = 0; s < 512; s++) {
        if (s == 0) {
            // One-time: convert hx (fp32) into hi/lo planes in smem
            const float* hsrc = hx + (size_t)b0 * 512;
#pragma unroll
            for (int i = 0; i < 8; i++) {
                int idx = t + 256 * i;
                int row = idx >> 7;
                int q   = idx & 127;
                float4 v = *(const float4*)&hsrc[(size_t)row * 512 + q * 4];
                float hx0 = __bfloat162float(__float2bfloat16_rn(v.x));
                float hy0 = __bfloat162float(__float2bfloat16_rn(v.y));
                float hz0 = __bfloat162float(__float2bfloat16_rn(v.z));
                float hw0 = __bfloat162float(__float2bfloat16_rn(v.w));
                uint2 hi = make_uint2(pack_bf16(v.x, v.y), pack_bf16(v.z, v.w));
                uint2 lo = make_uint2(pack_bf16(v.x - hx0, v.y - hy0),
                                      pack_bf16(v.z - hz0, v.w - hw0));
                uint32_t boff = (uint32_t)(row * SPITCH + q * 4) * 2;
                *(uint2*)(smem + S_OFF_HH + boff) = hi;
                *(uint2*)(smem + S_OFF_HL + boff) = lo;
            }
        } else {
            // Pure copy: 16 rows x 512 bf16 per plane = 64 uint4 per row
            const uint4* hh = (const uint4*)(g_hh[s & 1] + (size_t)b0 * 512);
            const uint4* hl = (const uint4*)(g_hl[s & 1] + (size_t)b0 * 512);
#pragma unroll
            for (int i = 0; i < 4; i++) {
                int idx = t + 256 * i;       // 0..1023
                int row = idx >> 6;          // 0..15
                int q   = idx & 63;
                uint32_t boff = (uint32_t)(row * SPITCH) * 2 + q * 16;
                *(uint4*)(smem + S_OFF_HH + boff) = hh[row * 64 + q];
                *(uint4*)(smem + S_OFF_HL + boff) = hl[row * 64 + q];
            }
        }

        // --- Prefetch gi / f (independent of MMA) ---
        size_t gib = ((size_t)s * 64 + bglob) * 1536 + c0 + ej;
        float i_r = g_gi[gib];
        float i_i = g_gi[gib + 512];
        float i_n = g_gi[gib + 1024];
        size_t fb = ((size_t)s * 64 + bglob) * 1024 + c0 + ej;
        float f_r = g_f[fb];
        float f_i = g_f[fb + 512];

        __syncthreads();   // h planes visible

        // --- MMA phase: gh partial over warp's K-slice (64) ---
        float acc[6][4];
#pragma unroll
        for (int nj = 0; nj < 6; nj++)
#pragma unroll
            for (int k = 0; k < 4; k++) acc[nj][k] = 0.f;

#pragma unroll
        for (int ks = 0; ks < 4; ks++) {
            uint32_t ah[4], al[4];
            int arow = lr + (lg & 1) * 8;
            int acol = w * 64 + ks * 16 + (lg >> 1) * 8;
            uint32_t aoff = (uint32_t)(arow * SPITCH + acol) * 2;
            LDMATRIX_X4(ah, sb + S_OFF_HH + aoff);
            LDMATRIX_X4(al, sb + S_OFF_HL + aoff);
#pragma unroll
            for (int np = 0; np < 3; np++)
#pragma unroll
                for (int sub = 0; sub < 2; sub++) {
                    int nj = np * 2 + sub;
                    MMA_BF16(acc[nj], ah, bfh[np][ks][2 * sub], bfh[np][ks][2 * sub + 1]);
                    MMA_BF16(acc[nj], ah, bfl[np][ks][2 * sub], bfl[np][ks][2 * sub + 1]);
                    MMA_BF16(acc[nj], al, bfh[np][ks][2 * sub], bfh[np][ks][2 * sub + 1]);
                }
        }

        // --- Store partials [m16 x n48], pitch 49 ---
        {
            float* red = redf + w * 784;
#pragma unroll
            for (int nj = 0; nj < 6; nj++)
#pragma unroll
                for (int half = 0; half < 2; half++) {
                    int m = qrow + half * 8;
                    int n = nj * 8 + qcol;
                    red[m * 49 + n]     = acc[nj][half * 2 + 0];
                    red[m * 49 + n + 1] = acc[nj][half * 2 + 1];
                }
        }
        __syncthreads();

        // --- Fused reduce + gate epilogue for (eb, ej) ---
        float h_r = bs[ej];
        float h_i = bs[16 + ej];
        float h_n = bs[32 + ej];
#pragma unroll
        for (int w2 = 0; w2 < 8; w2++) {
            const float* rr = redf + w2 * 784 + eb * 49;
            h_r += rr[ej];
            h_i += rr[16 + ej];
            h_n += rr[32 + ej];
        }
        float rgate = 1.f / (1.f + __expf(-(i_r + h_r + f_r)));
        float igate = 1.f / (1.f + __expf(-(i_i + h_i + f_i)));
        float ngate = tanhf(i_n + rgate * h_n);
        float hy = ngate + igate * (hprev - ngate);
        hprev = hy;

        // h for next step, hi/lo planes (conversion at the producer)
        {
            __nv_bfloat16 hhi = __float2bfloat16_rn(hy);
            float resid = hy - __bfloat162float(hhi);
            __nv_bfloat16 hlo = __float2bfloat16_rn(resid);
            size_t hidx = (size_t)bglob * 512 + c0 + ej;
            g_hh[(s + 1) & 1][hidx] = hhi;
            g_hl[(s + 1) & 1][hidx] = hlo;
        }

        __syncthreads();                   // all hy stores issued
        if (t == 0) {
            asm volatile("red.release.gpu.global.add.u32 [%0], %1;"
                         :: "l"(barp), "r"(1u) : "memory");
        }

        // out-row store overlaps other CTAs' barrier arrival
        out[((size_t)bglob * 512 + s) * 512 + c0 + ej] = hy;
        if (s == 511)
            out[(size_t)64 * 512 * 512 + (size_t)bglob * 512 + c0 + ej] = hy;

        if (t == 0) {
            unsigned target = (unsigned)(s + 1) * 32u;
            unsigned v;
            do {
                asm volatile("ld.acquire.gpu.global.u32 %0, [%1];"
                             : "=r"(v) : "l"(barp) : "memory");
            } while (v < target);
        }
        __syncthreads();
    }
}

// ---------------------------------------------------------------------------
// Launch
// ---------------------------------------------------------------------------
extern "C" void kernel_launch(void* const* d_in, const int* in_sizes, int n_in,
                              void* d_out, int out_size) {
    const float* input = (const float*)d_in[0];   // [B,S,D]
    const float* aux   = (const float*)d_in[1];   // [2,B,S,D]
    const float* hx    = (const float*)d_in[2];   // [B,H]
    const float* w_ih  = (const float*)d_in[3];   // [3H,D]
    const float* w_fh  = (const float*)d_in[4];   // [2,2H,D]
    const float* b_ih  = (const float*)d_in[5];   // [3H]
    const float* b_fh  = (const float*)d_in[6];   // [2,2H]
    const float* w_hh  = (const float*)d_in[7];   // [3H,H]
    const float* b_hh  = (const float*)d_in[8];   // [3H]
    float* out = (float*)d_out;

    cudaFuncSetAttribute(gemm_gi_mma,
                         cudaFuncAttributeMaxDynamicSharedMemorySize,
                         GEMM_SMEM_BYTES);
    cudaFuncSetAttribute(gemm_f_mma,
                         cudaFuncAttributeMaxDynamicSharedMemorySize,
                         GEMM_SMEM_BYTES);
    cudaFuncSetAttribute(scan_kernel,
                         cudaFuncAttributeMaxDynamicSharedMemorySize,
                         SCAN_SMEM_BYTES);

    init_bar_kernel<<<1, 32>>>();
    gemm_gi_mma<<<dim3(256, 12), 256, GEMM_SMEM_BYTES>>>(input, w_ih, b_ih);
    gemm_f_mma<<<dim3(256, 8), 256, GEMM_SMEM_BYTES>>>(aux, w_fh, b_fh);
    scan_kernel<<<128, 256, SCAN_SMEM_BYTES>>>(hx, w_hh, b_hh, out);
}

// round 12
// speedup vs baseline: 1.1578x; 1.0075x over previous
#include <cuda_runtime.h>
#include <cuda_bf16.h>
#include <math.h>
#include <stdint.h>

// Problem sizes (fixed)
#define BB 64     // batch
#define SS 512    // seq len
#define DD 512    // input dim
#define HH 512    // hidden

// ---------------------------------------------------------------------------
// Device scratch (allocation-free rule: device globals only)
// ---------------------------------------------------------------------------
__device__ float g_gi[(size_t)SS * BB * 3 * HH];   // [s][b][3H]
__device__ float g_f [(size_t)SS * BB * 2 * HH];   // [s][b][2H]
__device__ __nv_bfloat16 g_hh[2][BB * HH];         // h hi-plane ping-pong
__device__ __nv_bfloat16 g_hl[2][BB * HH];         // h lo-plane ping-pong
__device__ unsigned g_bar[4];                      // per-batch-group barrier

__global__ void init_bar_kernel() {
    if (threadIdx.x < 4) g_bar[threadIdx.x] = 0u;
}

// ---------------------------------------------------------------------------
// mma.sync helpers (sm_80+ vocabulary — works under compute_103 PTX)
// ---------------------------------------------------------------------------
__device__ __forceinline__ uint32_t smem_to_u32(const void* p) {
    uint32_t a;
    asm("{ .reg .u64 t; cvta.to.shared.u64 t, %1; cvt.u32.u64 %0, t; }"
        : "=r"(a) : "l"(p));
    return a;
}

#define LDMATRIX_X4(r, addr) \
    asm volatile("ldmatrix.sync.aligned.m8n8.x4.shared.b16 {%0,%1,%2,%3}, [%4];" \
        : "=r"((r)[0]), "=r"((r)[1]), "=r"((r)[2]), "=r"((r)[3]) : "r"(addr))

#define MMA_BF16(d, a, b0, b1) \
    asm volatile("mma.sync.aligned.m16n8k16.row.col.f32.bf16.bf16.f32 " \
        "{%0,%1,%2,%3}, {%4,%5,%6,%7}, {%8,%9}, {%0,%1,%2,%3};" \
        : "+f"((d)[0]), "+f"((d)[1]), "+f"((d)[2]), "+f"((d)[3]) \
        : "r"((a)[0]), "r"((a)[1]), "r"((a)[2]), "r"((a)[3]), \
          "r"(b0), "r"(b1))

__device__ __forceinline__ uint32_t pack_bf16(float a, float b) {
    return ((uint32_t)__bfloat16_as_ushort(__float2bfloat16_rn(b)) << 16) |
           (uint32_t)__bfloat16_as_ushort(__float2bfloat16_rn(a));
}

// ---------------------------------------------------------------------------
// Precompute GEMMs: CTA 128x128, BK=64, 256 threads (8 warps, 2x4, warp tile
// 64x32). bf16 hi/lo 3-pass split. Double-buffered, one sync per 64-K chunk.
// Grid ordering: n fastest -> n-blocks of one m-row co-resident, A-block
// shared via L2, W permanently L2-resident.
// ---------------------------------------------------------------------------
#define GP2 72                             // smem pitch in bf16 (144 B rows)
#define G2_TILE_B (128 * GP2 * 2)          // 18432 bytes per tile
#define OFF2(st, w) ((st) * 4 * G2_TILE_B + (w) * G2_TILE_B)
#define GEMM_SMEM_BYTES (8 * G2_TILE_B)    // 147456

// Load one [128 x 32] fp32 sub-chunk (row stride 512): 4 float4 per thread.
__device__ __forceinline__ void ldg_sub(const float* __restrict__ src,
                                        float4 v[4], int t) {
#pragma unroll
    for (int i = 0; i < 4; i++) {
        int idx = t + 256 * i;
        int row = idx >> 3;
        int kq  = idx & 7;
        v[i] = *(const float4*)(src + (size_t)row * 512 + kq * 4);
    }
}

// Convert + store one sub-chunk into hi/lo tiles at K offset ksub*32.
__device__ __forceinline__ void sts_sub(char* smem, int hi_off, int lo_off,
                                        const float4 v[4], int t, int ksub) {
#pragma unroll
    for (int i = 0; i < 4; i++) {
        int idx = t + 256 * i;
        int row = idx >> 3;
        int kq  = idx & 7;
        float4 x = v[i];
        float hx = __bfloat162float(__float2bfloat16_rn(x.x));
        float hy = __bfloat162float(__float2bfloat16_rn(x.y));
        float hz = __bfloat162float(__float2bfloat16_rn(x.z));
        float hw = __bfloat162float(__float2bfloat16_rn(x.w));
        uint2 hi = make_uint2(pack_bf16(x.x, x.y), pack_bf16(x.z, x.w));
        uint2 lo = make_uint2(pack_bf16(x.x - hx, x.y - hy),
                              pack_bf16(x.z - hz, x.w - hw));
        uint32_t boff = (uint32_t)(row * GP2 + ksub * 32 + kq * 4) * 2;
        *(uint2*)(smem + hi_off + boff) = hi;
        *(uint2*)(smem + lo_off + boff) = lo;
    }
}

// One k16 step: warp tile 64(M) x 32(N): 12 ldmatrix.x4 + 48 mma.
__device__ __forceinline__ void warp_k16(uint32_t sb, int buf, int ks,
                                         int wm, int wn, int lane,
                                         float acc[4][4][4]) {
    const int lr = lane & 7;
    const int lg = lane >> 3;
    uint32_t ah[4][4], al[4][4];
#pragma unroll
    for (int mt = 0; mt < 4; mt++) {
        int arow = wm * 64 + mt * 16 + lr + (lg & 1) * 8;
        int acol = ks * 16 + (lg >> 1) * 8;
        uint32_t boff = (uint32_t)(arow * GP2 + acol) * 2;
        LDMATRIX_X4(ah[mt], sb + OFF2(buf, 0) + boff);
        LDMATRIX_X4(al[mt], sb + OFF2(buf, 1) + boff);
    }
    uint32_t bh[2][4], bl[2][4];
#pragma unroll
    for (int np = 0; np < 2; np++) {
        int brow = wn * 32 + np * 16 + lr + (lg >> 1) * 8;
        int bcol = ks * 16 + (lg & 1) * 8;
        uint32_t boff = (uint32_t)(brow * GP2 + bcol) * 2;
        LDMATRIX_X4(bh[np], sb + OFF2(buf, 2) + boff);
        LDMATRIX_X4(bl[np], sb + OFF2(buf, 3) + boff);
    }
#pragma unroll
    for (int mt = 0; mt < 4; mt++)
#pragma unroll
        for (int np = 0; np < 2; np++)
#pragma unroll
            for (int sub = 0; sub < 2; sub++) {
                int nj = np * 2 + sub;
                MMA_BF16(acc[mt][nj], ah[mt], bh[np][2 * sub], bh[np][2 * sub + 1]);
                MMA_BF16(acc[mt][nj], ah[mt], bl[np][2 * sub], bl[np][2 * sub + 1]);
                MMA_BF16(acc[mt][nj], al[mt], bh[np][2 * sub], bh[np][2 * sub + 1]);
            }
}

__global__ __launch_bounds__(256, 1) void gemm_gi_mma(
    const float* __restrict__ A, const float* __restrict__ W,
    const float* __restrict__ bias)
{
    extern __shared__ char smem[];
    uint32_t sb = smem_to_u32(smem);
    const int t = threadIdx.x;
    const int wid = t >> 5;
    const int lane = t & 31;
    const int wm = wid & 1;
    const int wn = wid >> 1;
    const int m0 = blockIdx.y * 128;   // n fastest: x = n-tile, y = m-tile
    const int n0 = blockIdx.x * 128;

    float acc[4][4][4];
#pragma unroll
    for (int i = 0; i < 4; i++)
#pragma unroll
        for (int j = 0; j < 4; j++)
#pragma unroll
            for (int k = 0; k < 4; k++) acc[i][j][k] = 0.f;

    const float* Abase = A + (size_t)m0 * 512;
    const float* Wbase = W + (size_t)n0 * 512;

    float4 a0[4], a1[4], b0[4], b1[4];
    // Fill buffer 0 with chunk 0 (K 0..63)
    ldg_sub(Abase, a0, t);
    ldg_sub(Abase + 32, a1, t);
    ldg_sub(Wbase, b0, t);
    ldg_sub(Wbase + 32, b1, t);
    sts_sub(smem, OFF2(0, 0), OFF2(0, 1), a0, t, 0);
    sts_sub(smem, OFF2(0, 0), OFF2(0, 1), a1, t, 1);
    sts_sub(smem, OFF2(0, 2), OFF2(0, 3), b0, t, 0);
    sts_sub(smem, OFF2(0, 2), OFF2(0, 3), b1, t, 1);
    __syncthreads();

    const int NC = 8;   // 512 / 64
    for (int c = 0; c < NC; c++) {
        int buf = c & 1;
        if (c + 1 < NC) {
            const float* Ac = Abase + (c + 1) * 64;
            const float* Wc = Wbase + (c + 1) * 64;
            ldg_sub(Ac, a0, t);
            ldg_sub(Ac + 32, a1, t);
            ldg_sub(Wc, b0, t);
            ldg_sub(Wc + 32, b1, t);
        }
        warp_k16(sb, buf, 0, wm, wn, lane, acc);
        warp_k16(sb, buf, 1, wm, wn, lane, acc);
        if (c + 1 < NC) {
            int nb = buf ^ 1;
            sts_sub(smem, OFF2(nb, 0), OFF2(nb, 1), a0, t, 0);
            sts_sub(smem, OFF2(nb, 0), OFF2(nb, 1), a1, t, 1);
            sts_sub(smem, OFF2(nb, 2), OFF2(nb, 3), b0, t, 0);
            sts_sub(smem, OFF2(nb, 2), OFF2(nb, 3), b1, t, 1);
        }
        warp_k16(sb, buf, 2, wm, wn, lane, acc);
        warp_k16(sb, buf, 3, wm, wn, lane, acc);
        __syncthreads();
    }

    const int qrow = lane >> 2;
    const int qcol = (lane & 3) * 2;
#pragma unroll
    for (int mt = 0; mt < 4; mt++)
#pragma unroll
        for (int half = 0; half < 2; half++) {
            int m = m0 + wm * 64 + mt * 16 + qrow + half * 8;
            int b = m >> 9;
            int s = m & 511;
            float* crow = &g_gi[((size_t)s * 64 + b) * 1536 + n0 + wn * 32];
#pragma unroll
            for (int nj = 0; nj < 4; nj++) {
                int n = nj * 8 + qcol;
                float2 bvv = *(const float2*)&bias[n0 + wn * 32 + n];
                float2 o;
                o.x = acc[mt][nj][half * 2 + 0] + bvv.x;
                o.y = acc[mt][nj][half * 2 + 1] + bvv.y;
                *(float2*)&crow[n] = o;
            }
        }
}

__global__ __launch_bounds__(256, 1) void gemm_f_mma(
    const float* __restrict__ Aux, const float* __restrict__ Wf,
    const float* __restrict__ bf)
{
    extern __shared__ char smem[];
    uint32_t sb = smem_to_u32(smem);
    const int t = threadIdx.x;
    const int wid = t >> 5;
    const int lane = t & 31;
    const int wm = wid & 1;
    const int wn = wid >> 1;
    const int m0 = blockIdx.y * 128;   // n fastest
    const int n0 = blockIdx.x * 128;

    float acc[4][4][4];
#pragma unroll
    for (int i = 0; i < 4; i++)
#pragma unroll
        for (int j = 0; j < 4; j++)
#pragma unroll
            for (int k = 0; k < 4; k++) acc[i][j][k] = 0.f;

    float4 a0[4], a1[4], b0[4], b1[4];
    const float* A0 = Aux + (size_t)m0 * 512;
    const float* W0 = Wf + (size_t)n0 * 512;
    ldg_sub(A0, a0, t);
    ldg_sub(A0 + 32, a1, t);
    ldg_sub(W0, b0, t);
    ldg_sub(W0 + 32, b1, t);
    sts_sub(smem, OFF2(0, 0), OFF2(0, 1), a0, t, 0);
    sts_sub(smem, OFF2(0, 0), OFF2(0, 1), a1, t, 1);
    sts_sub(smem, OFF2(0, 2), OFF2(0, 3), b0, t, 0);
    sts_sub(smem, OFF2(0, 2), OFF2(0, 3), b1, t, 1);
    __syncthreads();

    const int NC = 16;  // 2 segments x 8 chunks of 64K
    for (int c = 0; c < NC; c++) {
        int buf = c & 1;
        if (c + 1 < NC) {
            int cn = c + 1;
            int seg = cn >> 3, kk = cn & 7;
            const float* Ac = Aux + (size_t)seg * 32768 * 512 + (size_t)m0 * 512 + kk * 64;
            const float* Wc = Wf + (size_t)seg * 1024 * 512 + (size_t)n0 * 512 + kk * 64;
            ldg_sub(Ac, a0, t);
            ldg_sub(Ac + 32, a1, t);
            ldg_sub(Wc, b0, t);
            ldg_sub(Wc + 32, b1, t);
        }
        warp_k16(sb, buf, 0, wm, wn, lane, acc);
        warp_k16(sb, buf, 1, wm, wn, lane, acc);
        if (c + 1 < NC) {
            int nb = buf ^ 1;
            sts_sub(smem, OFF2(nb, 0), OFF2(nb, 1), a0, t, 0);
            sts_sub(smem, OFF2(nb, 0), OFF2(nb, 1), a1, t, 1);
            sts_sub(smem, OFF2(nb, 2), OFF2(nb, 3), b0, t, 0);
            sts_sub(smem, OFF2(nb, 2), OFF2(nb, 3), b1, t, 1);
        }
        warp_k16(sb, buf, 2, wm, wn, lane, acc);
        warp_k16(sb, buf, 3, wm, wn, lane, acc);
        __syncthreads();
    }

    const int qrow = lane >> 2;
    const int qcol = (lane & 3) * 2;
#pragma unroll
    for (int mt = 0; mt < 4; mt++)
#pragma unroll
        for (int half = 0; half < 2; half++) {
            int m = m0 + wm * 64 + mt * 16 + qrow + half * 8;
            int b = m >> 9;
            int s = m & 511;
            float* crow = &g_f[((size_t)s * 64 + b) * 1024 + n0 + wn * 32];
#pragma unroll
            for (int nj = 0; nj < 4; nj++) {
                int n = nj * 8 + qcol;
                int ng = n0 + wn * 32 + n;
                float2 c0 = *(const float2*)&bf[ng];
                float2 c1 = *(const float2*)&bf[1024 + ng];
                float2 o;
                o.x = 0.5f * acc[mt][nj][half * 2 + 0] + 0.5f * (c0.x + c1.x);
                o.y = 0.5f * acc[mt][nj][half * 2 + 1] + 0.5f * (c0.y + c1.y);
                *(float2*)&crow[n] = o;
            }
        }
}

// ---------------------------------------------------------------------------
// Persistent recurrent scan — byte-identical to the passing round-11 kernel.
// 256 threads, producer-side bf16 hi/lo h exchange, fused reduce+epilogue.
// Grid 128 = 4 batch-groups (16 b) x 32 column-CTAs (16 hy cols = 48 W rows).
// ---------------------------------------------------------------------------
#define SPITCH 520                       // bf16 pitch
#define S_OFF_WH  0                      // 48 x 520 bf16 = 49920 B
#define S_OFF_WL  49920
#define S_OFF_HH  99840                  // 16 x 520 bf16 = 16640 B
#define S_OFF_HL  116480
#define S_OFF_RED 133120                 // 8 x 784 fp32 = 25088 B
#define S_OFF_BS  158208                 // 48 fp32
#define SCAN_SMEM_BYTES 158400

__global__ __launch_bounds__(256, 1) void scan_kernel(
    const float* __restrict__ hx, const float* __restrict__ Whh,
    const float* __restrict__ bias_hh, float* __restrict__ out)
{
    extern __shared__ char smem[];
    uint32_t sb = smem_to_u32(smem);
    float* redf = (float*)(smem + S_OFF_RED);
    float* bs   = (float*)(smem + S_OFF_BS);

    const int t    = threadIdx.x;
    const int w    = t >> 5;               // warp 0..7 (K-slice 64 each)
    const int lane = t & 31;
    const int lr   = lane & 7;
    const int lg   = lane >> 3;
    const int gid  = blockIdx.x >> 5;
    const int cid  = blockIdx.x & 31;
    const int b0   = gid * 16;
    const int c0   = cid * 16;

    // --- Stage W_hh slice as bf16 hi/lo into smem (once) ---
    for (int i = t; i < 48 * 128; i += 256) {
        int r = i >> 7;
        int q = i & 127;
        int gate = r >> 4, j = r & 15;
        float4 v = *(const float4*)&Whh[(size_t)(gate * 512 + c0 + j) * 512 + q * 4];
        float hx0 = __bfloat162float(__float2bfloat16_rn(v.x));
        float hy0 = __bfloat162float(__float2bfloat16_rn(v.y));
        float hz0 = __bfloat162float(__float2bfloat16_rn(v.z));
        float hw0 = __bfloat162float(__float2bfloat16_rn(v.w));
        uint2 hi = make_uint2(pack_bf16(v.x, v.y), pack_bf16(v.z, v.w));
        uint2 lo = make_uint2(pack_bf16(v.x - hx0, v.y - hy0),
                              pack_bf16(v.z - hz0, v.w - hw0));
        uint32_t boff = (uint32_t)(r * SPITCH + q * 4) * 2;
        *(uint2*)(smem + S_OFF_WH + boff) = hi;
        *(uint2*)(smem + S_OFF_WL + boff) = lo;
    }
    if (t < 48) {
        int gate = t >> 4, j = t & 15;
        bs[t] = bias_hh[gate * 512 + c0 + j];
    }
    __syncthreads();

    // --- W fragments in registers: per warp 3 n16-groups x 4 k16 (hi/lo) ---
    uint32_t bfh[3][4][4], bfl[3][4][4];
#pragma unroll
    for (int np = 0; np < 3; np++)
#pragma unroll
        for (int ks = 0; ks < 4; ks++) {
            int brow = np * 16 + lr + (lg >> 1) * 8;
            int bcol = w * 64 + ks * 16 + (lg & 1) * 8;
            uint32_t boff = (uint32_t)(brow * SPITCH + bcol) * 2;
            LDMATRIX_X4(bfh[np][ks], sb + S_OFF_WH + boff);
            LDMATRIX_X4(bfl[np][ks], sb + S_OFF_WL + boff);
        }

    const int eb = t >> 4;                 // epilogue batch 0..15
    const int ej = t & 15;                 // epilogue column 0..15
    const int bglob = b0 + eb;
    const int qrow = lane >> 2;
    const int qcol = (lane & 3) * 2;

    unsigned* barp = &g_bar[gid];

    // hprev carried in register (exact fp32): this thread owns (bglob, c0+ej)
    float hprev = hx[(size_t)bglob * 512 + c0 + ej];

    for (int s = 0; s < 512; s++) {
        if (s == 0) {
            // One-time: convert hx (fp32) into hi/lo planes in smem
            const float* hsrc = hx + (size_t)b0 * 512;
#pragma unroll
            for (int i = 0; i < 8; i++) {
                int idx = t + 256 * i;
                int row = idx >> 7;
                int q   = idx & 127;
                float4 v = *(const float4*)&hsrc[(size_t)row * 512 + q * 4];
                float hx0 = __bfloat162float(__float2bfloat16_rn(v.x));
                float hy0 = __bfloat162float(__float2bfloat16_rn(v.y));
                float hz0 = __bfloat162float(__float2bfloat16_rn(v.z));
                float hw0 = __bfloat162float(__float2bfloat16_rn(v.w));
                uint2 hi = make_uint2(pack_bf16(v.x, v.y), pack_bf16(v.z, v.w));
                uint2 lo = make_uint2(pack_bf16(v.x - hx0, v.y - hy0),
                                      pack_bf16(v.z - hz0, v.w - hw0));
                uint32_t boff = (uint32_t)(row * SPITCH + q * 4) * 2;
                *(uint2*)(smem + S_OFF_HH + boff) = hi;
                *(uint2*)(smem + S_OFF_HL + boff) = lo;
            }
        } else {
            // Pure copy: 16 rows x 512 bf16 per plane = 64 uint4 per row
            const uint4* hh = (const uint4*)(g_hh[s & 1] + (size_t)b0 * 512);
            const uint4* hl = (const uint4*)(g_hl[s & 1] + (size_t)b0 * 512);
#pragma unroll
            for (int i = 0; i < 4; i++) {
                int idx = t + 256 * i;       // 0..1023
                int row = idx >> 6;          // 0..15
                int q   = idx & 63;
                uint32_t boff = (uint32_t)(row * SPITCH) * 2 + q * 16;
                *(uint4*)(smem + S_OFF_HH + boff) = hh[row * 64 + q];
                *(uint4*)(smem + S_OFF_HL + boff) = hl[row * 64 + q];
            }
        }

        // --- Prefetch gi / f (independent of MMA) ---
        size_t gib = ((size_t)s * 64 + bglob) * 1536 + c0 + ej;
        float i_r = g_gi[gib];
        float i_i = g_gi[gib + 512];
        float i_n = g_gi[gib + 1024];
        size_t fb = ((size_t)s * 64 + bglob) * 1024 + c0 + ej;
        float f_r = g_f[fb];
        float f_i = g_f[fb + 512];

        __syncthreads();   // h planes visible

        // --- MMA phase: gh partial over warp's K-slice (64) ---
        float acc[6][4];
#pragma unroll
        for (int nj = 0; nj < 6; nj++)
#pragma unroll
            for (int k = 0; k < 4; k++) acc[nj][k] = 0.f;

#pragma unroll
        for (int ks = 0; ks < 4; ks++) {
            uint32_t ah[4], al[4];
            int arow = lr + (lg & 1) * 8;
            int acol = w * 64 + ks * 16 + (lg >> 1) * 8;
            uint32_t aoff = (uint32_t)(arow * SPITCH + acol) * 2;
            LDMATRIX_X4(ah, sb + S_OFF_HH + aoff);
            LDMATRIX_X4(al, sb + S_OFF_HL + aoff);
#pragma unroll
            for (int np = 0; np < 3; np++)
#pragma unroll
                for (int sub = 0; sub < 2; sub++) {
                    int nj = np * 2 + sub;
                    MMA_BF16(acc[nj], ah, bfh[np][ks][2 * sub], bfh[np][ks][2 * sub + 1]);
                    MMA_BF16(acc[nj], ah, bfl[np][ks][2 * sub], bfl[np][ks][2 * sub + 1]);
                    MMA_BF16(acc[nj], al, bfh[np][ks][2 * sub], bfh[np][ks][2 * sub + 1]);
                }
        }

        // --- Store partials [m16 x n48], pitch 49 ---
        {
            float* red = redf + w * 784;
#pragma unroll
            for (int nj = 0; nj < 6; nj++)
#pragma unroll
                for (int half = 0; half < 2; half++) {
                    int m = qrow + half * 8;
                    int n = nj * 8 + qcol;
                    red[m * 49 + n]     = acc[nj][half * 2 + 0];
                    red[m * 49 + n + 1] = acc[nj][half * 2 + 1];
                }
        }
        __syncthreads();

        // --- Fused reduce + gate epilogue for (eb, ej) ---
        float h_r = bs[ej];
        float h_i = bs[16 + ej];
        float h_n = bs[32 + ej];
#pragma unroll
        for (int w2 = 0; w2 < 8; w2++) {
            const float* rr = redf + w2 * 784 + eb * 49;
            h_r += rr[ej];
            h_i += rr[16 + ej];
            h_n += rr[32 + ej];
        }
        float rgate = 1.f / (1.f + __expf(-(i_r + h_r + f_r)));
        float igate = 1.f / (1.f + __expf(-(i_i + h_i + f_i)));
        float ngate = tanhf(i_n + rgate * h_n);
        float hy = ngate + igate * (hprev - ngate);
        hprev = hy;

        // h for next step, hi/lo planes (conversion at the producer)
        {
            __nv_bfloat16 hhi = __float2bfloat16_rn(hy);
            float resid = hy - __bfloat162float(hhi);
            __nv_bfloat16 hlo = __float2bfloat16_rn(resid);
            size_t hidx = (size_t)bglob * 512 + c0 + ej;
            g_hh[(s + 1) & 1][hidx] = hhi;
            g_hl[(s + 1) & 1][hidx] = hlo;
        }

        __syncthreads();                   // all hy stores issued
        if (t == 0) {
            asm volatile("red.release.gpu.global.add.u32 [%0], %1;"
                         :: "l"(barp), "r"(1u) : "memory");
        }

        // out-row store overlaps other CTAs' barrier arrival
        out[((size_t)bglob * 512 + s) * 512 + c0 + ej] = hy;
        if (s == 511)
            out[(size_t)64 * 512 * 512 + (size_t)bglob * 512 + c0 + ej] = hy;

        if (t == 0) {
            unsigned target = (unsigned)(s + 1) * 32u;
            unsigned v;
            do {
                asm volatile("ld.acquire.gpu.global.u32 %0, [%1];"
                             : "=r"(v) : "l"(barp) : "memory");
            } while (v < target);
        }
        __syncthreads();
    }
}

// ---------------------------------------------------------------------------
// Launch
// ---------------------------------------------------------------------------
extern "C" void kernel_launch(void* const* d_in, const int* in_sizes, int n_in,
                              void* d_out, int out_size) {
    const float* input = (const float*)d_in[0];   // [B,S,D]
    const float* aux   = (const float*)d_in[1];   // [2,B,S,D]
    const float* hx    = (const float*)d_in[2];   // [B,H]
    const float* w_ih  = (const float*)d_in[3];   // [3H,D]
    const float* w_fh  = (const float*)d_in[4];   // [2,2H,D]
    const float* b_ih  = (const float*)d_in[5];   // [3H]
    const float* b_fh  = (const float*)d_in[6];   // [2,2H]
    const float* w_hh  = (const float*)d_in[7];   // [3H,H]
    const float* b_hh  = (const float*)d_in[8];   // [3H]
    float* out = (float*)d_out;

    cudaFuncSetAttribute(gemm_gi_mma,
                         cudaFuncAttributeMaxDynamicSharedMemorySize,
                         GEMM_SMEM_BYTES);
    cudaFuncSetAttribute(gemm_f_mma,
                         cudaFuncAttributeMaxDynamicSharedMemorySize,
                         GEMM_SMEM_BYTES);
    cudaFuncSetAttribute(scan_kernel,
                         cudaFuncAttributeMaxDynamicSharedMemorySize,
                         SCAN_SMEM_BYTES);

    init_bar_kernel<<<1, 32>>>();
    // n-tile fastest (x), m-tile slow (y): A-block shared via L2 across the
    // co-resident n-blocks; W fully L2-resident.
    gemm_gi_mma<<<dim3(12, 256), 256, GEMM_SMEM_BYTES>>>(input, w_ih, b_ih);
    gemm_f_mma<<<dim3(8, 256), 256, GEMM_SMEM_BYTES>>>(aux, w_fh, b_fh);
    scan_kernel<<<128, 256, SCAN_SMEM_BYTES>>>(hx, w_hh, b_hh, out);
}